// round 7
// baseline (speedup 1.0000x reference)
#include <cuda_runtime.h>
#include <cuda_bf16.h>

#define S1   2048
#define S2   4096
#define HIDN 1024
#define NH   8
#define HD   128
#define INTER_ 4096

// ---------------- scratch ----------------
__device__ float g_H [S1 * HIDN];
__device__ float g_H1[S1 * HIDN];
__device__ float g_Q [S2 * HIDN];
__device__ float g_K [S2 * HIDN];
__device__ float g_V [S2 * HIDN];
__device__ float g_QR[S1 * HIDN];
__device__ float g_KR[S1 * HIDN];
__device__ float g_ATTN[S2 * HIDN];
__device__ float g_MIXO[S1 * HIDN];
__device__ float g_G[S1 * INTER_];
__device__ float g_U[S1 * INTER_];

// ---------------- NN GEMM ----------------
template<bool HAS_E>
__global__ __launch_bounds__(256)
void gemm2_kernel(const float* __restrict__ A, const float* __restrict__ B,
                  float* __restrict__ C, const float* __restrict__ E,
                  int M, int N, int K, int lda, int ldb, int ldc, int lde, float alpha)
{
    __shared__ float sa[16][65];
    __shared__ float sb[16][65];

    const int bm = blockIdx.y * 64;
    const int bn = blockIdx.x * 64;
    const int tid = threadIdx.x;
    const int tx = tid & 15;
    const int ty = tid >> 4;

    float acc[4][4];
#pragma unroll
    for (int i = 0; i < 4; i++)
#pragma unroll
        for (int j = 0; j < 4; j++) acc[i][j] = 0.f;

    for (int k0 = 0; k0 < K; k0 += 16) {
        for (int i = tid; i < 64 * 16; i += 256) {
            int m = i >> 4, k = i & 15;
            sa[k][m] = A[(long)(bm + m) * lda + (k0 + k)];
        }
        for (int i = tid; i < 16 * 64; i += 256) {
            int k = i >> 6, n = i & 63;
            sb[k][n] = B[(long)(k0 + k) * ldb + (bn + n)];
        }
        __syncthreads();

#pragma unroll
        for (int kk = 0; kk < 16; kk++) {
            float a[4], b[4];
#pragma unroll
            for (int i = 0; i < 4; i++) a[i] = sa[kk][ty * 4 + i];
#pragma unroll
            for (int j = 0; j < 4; j++) b[j] = sb[kk][tx * 4 + j];
#pragma unroll
            for (int i = 0; i < 4; i++)
#pragma unroll
                for (int j = 0; j < 4; j++)
                    acc[i][j] = fmaf(a[i], b[j], acc[i][j]);
        }
        __syncthreads();
    }

#pragma unroll
    for (int i = 0; i < 4; i++) {
        int row = bm + ty * 4 + i;
#pragma unroll
        for (int j = 0; j < 4; j++) {
            int col = bn + tx * 4 + j;
            float v = alpha * acc[i][j];
            if (HAS_E) v += E[(long)row * lde + col];
            C[(long)row * ldc + col] = v;
        }
    }
}

// ---------------- flash attention ----------------
#define FA_BM 64
#define FA_BN 64

__global__ __launch_bounds__(256)
void flash_kernel(const float* __restrict__ Qp, const float* __restrict__ Kp,
                  const float* __restrict__ Vp, const float* __restrict__ Mask,
                  float* __restrict__ Op, int L, float scale)
{
    extern __shared__ float sm[];
    float* Qs = sm;
    float* Ks = Qs + 128 * FA_BM;
    float* Vs = Ks + 128 * FA_BN;
    float* Ss = Vs + FA_BN * 128;
    float* mrow = Ss + FA_BM * 65;
    float* lrow = mrow + FA_BM;
    float* arow = lrow + FA_BM;

    const int h   = blockIdx.z;
    const int q0  = blockIdx.x * FA_BM;
    const int tid = threadIdx.x;
    const int tx  = tid & 15;
    const int ty  = tid >> 4;

    const float* Qh = Qp + h * HD;
    const float* Kh = Kp + h * HD;
    const float* Vh = Vp + h * HD;

    for (int i = tid; i < FA_BM * 32; i += 256) {
        int m = i >> 5, d4 = (i & 31) * 4;
        float4 v = *(const float4*)(Qh + (long)(q0 + m) * HIDN + d4);
        Qs[(d4 + 0) * FA_BM + m] = v.x;
        Qs[(d4 + 1) * FA_BM + m] = v.y;
        Qs[(d4 + 2) * FA_BM + m] = v.z;
        Qs[(d4 + 3) * FA_BM + m] = v.w;
    }
    if (tid < FA_BM) { mrow[tid] = -3.4e38f; lrow[tid] = 0.f; }

    float Oacc[4][8];
#pragma unroll
    for (int i = 0; i < 4; i++)
#pragma unroll
        for (int j = 0; j < 8; j++) Oacc[i][j] = 0.f;

    __syncthreads();

    for (int k0 = 0; k0 < L; k0 += FA_BN) {
        for (int i = tid; i < FA_BN * 32; i += 256) {
            int n = i >> 5, d4 = (i & 31) * 4;
            float4 kv = *(const float4*)(Kh + (long)(k0 + n) * HIDN + d4);
            Ks[(d4 + 0) * FA_BN + n] = kv.x;
            Ks[(d4 + 1) * FA_BN + n] = kv.y;
            Ks[(d4 + 2) * FA_BN + n] = kv.z;
            Ks[(d4 + 3) * FA_BN + n] = kv.w;
            float4 vv = *(const float4*)(Vh + (long)(k0 + n) * HIDN + d4);
            *(float4*)(Vs + n * 128 + d4) = vv;
        }
        __syncthreads();

        {
            float acc[4][4];
#pragma unroll
            for (int i = 0; i < 4; i++)
#pragma unroll
                for (int j = 0; j < 4; j++) acc[i][j] = 0.f;

            for (int d = 0; d < 128; d++) {
                float4 a4 = *(const float4*)(Qs + d * FA_BM + ty * 4);
                float4 b4 = *(const float4*)(Ks + d * FA_BN + tx * 4);
                float a[4] = {a4.x, a4.y, a4.z, a4.w};
                float b[4] = {b4.x, b4.y, b4.z, b4.w};
#pragma unroll
                for (int i = 0; i < 4; i++)
#pragma unroll
                    for (int j = 0; j < 4; j++)
                        acc[i][j] = fmaf(a[i], b[j], acc[i][j]);
            }
#pragma unroll
            for (int i = 0; i < 4; i++) {
                int row = q0 + ty * 4 + i;
#pragma unroll
                for (int j = 0; j < 4; j++) {
                    int col = k0 + tx * 4 + j;
                    Ss[(ty * 4 + i) * 65 + tx * 4 + j] =
                        acc[i][j] * scale + Mask[(long)row * L + col];
                }
            }
        }
        __syncthreads();

        if (tid < FA_BM) {
            float mold = mrow[tid];
            float mx = mold;
            for (int j = 0; j < FA_BN; j++) mx = fmaxf(mx, Ss[tid * 65 + j]);
            float alpha = expf(mold - mx);
            float sum = 0.f;
            for (int j = 0; j < FA_BN; j++) {
                float p = expf(Ss[tid * 65 + j] - mx);
                Ss[tid * 65 + j] = p;
                sum += p;
            }
            mrow[tid] = mx;
            lrow[tid] = lrow[tid] * alpha + sum;
            arow[tid] = alpha;
        }
        __syncthreads();

        {
            int oy = ty * 4;
#pragma unroll
            for (int i = 0; i < 4; i++) {
                float a = arow[oy + i];
#pragma unroll
                for (int j = 0; j < 8; j++) Oacc[i][j] *= a;
            }
            for (int n = 0; n < FA_BN; n++) {
                float p[4];
#pragma unroll
                for (int i = 0; i < 4; i++) p[i] = Ss[(oy + i) * 65 + n];
#pragma unroll
                for (int j = 0; j < 8; j++) {
                    float v = Vs[n * 128 + tx + 16 * j];
#pragma unroll
                    for (int i = 0; i < 4; i++)
                        Oacc[i][j] = fmaf(p[i], v, Oacc[i][j]);
                }
            }
        }
        __syncthreads();
    }

    int oy = ty * 4;
#pragma unroll
    for (int i = 0; i < 4; i++) {
        float inv = 1.f / lrow[oy + i];
#pragma unroll
        for (int j = 0; j < 8; j++)
            Op[(long)(q0 + oy + i) * HIDN + h * HD + tx + 16 * j] = Oacc[i][j] * inv;
    }
}
#define FLASH_SMEM ((128*FA_BM + 128*FA_BN + FA_BN*128 + FA_BM*65 + 3*FA_BM) * 4)

// ---------------- RMSNorm ----------------
__global__ __launch_bounds__(256)
void rmsnorm_kernel(const float* __restrict__ x, const float* __restrict__ w,
                    float* __restrict__ out)
{
    long row = blockIdx.x;
    const float* xr = x + row * HIDN;
    float* o = out + row * HIDN;
    int t = threadIdx.x;
    __shared__ float part[256];
    float ss = 0.f;
    for (int c = t; c < HIDN; c += 256) { float v = xr[c]; ss += v * v; }
    part[t] = ss; __syncthreads();
    for (int w2 = 128; w2 > 0; w2 >>= 1) {
        if (t < w2) part[t] += part[t + w2];
        __syncthreads();
    }
    float inv = rsqrtf(part[0] / (float)HIDN + 1e-6f);
    for (int c = t; c < HIDN; c += 256) o[c] = xr[c] * inv * (1.f + w[c]);
}

// ---------------- RoPE, transcribed literally from the reference ----------------
// inv = 1.0 / THETA ** (arange(0, HD, 2) / HD)        (fp32 pow, like jnp)
// f   = outer(t, inv)                                  (fp32 multiply, like jnp)
// cos/sin of that fp32 angle, computed in double (accurate range reduction,
// matching XLA's accurate fp32 trig), then rounded to fp32.
// out[d]    = x[d]*cos - x[d+64]*sin
// out[d+64] = x[d+64]*cos + x[d]*sin
__global__ __launch_bounds__(256)
void rope2_kernel(const float* __restrict__ in, float* __restrict__ out, int S)
{
    int idx = blockIdx.x * 256 + threadIdx.x;
    if (idx >= S * NH * 64) return;
    int d = idx & 63;          // pair index 0..63
    int h = (idx >> 6) & 7;    // head
    int s = idx >> 9;          // position

    float inv = __powf(10000.0f, -((float)(2 * d)) / 128.0f);  // reference formula
    float ang = (float)s * inv;                                 // fp32 rounding, like outer()
    double cd, sd;
    sincos((double)ang, &sd, &cd);
    float c  = (float)cd;
    float sn = (float)sd;

    const float* ir = in + (long)s * HIDN + h * HD;
    float* orow = out + (long)s * HIDN + h * HD;
    float x0 = ir[d], x1 = ir[d + 64];
    orow[d]      = x0 * c - x1 * sn;
    orow[d + 64] = x1 * c + x0 * sn;
}

// ---------------- gelu(tanh)(g) * u, tanh via exp (restructured) ----------------
__global__ __launch_bounds__(256)
void gelumul2_kernel(float* __restrict__ g, const float* __restrict__ u, int n)
{
    int i = blockIdx.x * 256 + threadIdx.x;
    if (i >= n) return;
    float x = g[i];
    float z = 0.7978845608028654f * (x + 0.044715f * x * x * x);
    // tanh(z) = 1 - 2/(exp(2z)+1); exp overflow -> inf -> 1, underflow -> 0 -> -1 (both correct)
    float th = 1.f - 2.f / (expf(2.f * z) + 1.f);
    float t = 0.5f * x * (1.f + th);
    g[i] = t * u[i];
}

// ---------------- o[i] += a[i] ----------------
__global__ __launch_bounds__(256)
void add_kernel(float* __restrict__ o, const float* __restrict__ a, int n)
{
    int i = blockIdx.x * 256 + threadIdx.x;
    if (i < n) o[i] += a[i];
}

// ---------------- host helpers ----------------
static void gemm2(const float* A, const float* B, float* C, const float* E,
                  int M, int N, int K, int lda, int ldb, int ldc, int lde, float alpha)
{
    dim3 grid(N / 64, M / 64, 1);
    if (E) gemm2_kernel<true ><<<grid, 256>>>(A, B, C, E, M, N, K, lda, ldb, ldc, lde, alpha);
    else   gemm2_kernel<false><<<grid, 256>>>(A, B, C, E, M, N, K, lda, ldb, ldc, lde, alpha);
}

extern "C" void kernel_launch(void* const* d_in, const int* in_sizes, int n_in,
                              void* d_out, int out_size)
{
    (void)in_sizes; (void)n_in; (void)out_size;

    const float* x[2]    = { (const float*)d_in[0], (const float*)d_in[1] };
    const float* mask[2] = { (const float*)d_in[2], (const float*)d_in[3] };
    const float* mixmask = (const float*)d_in[4];
    float* out = (float*)d_out;

    float *H, *H1, *Q, *K, *V, *QR, *KR, *ATTN, *MIXO, *G, *U;
    cudaGetSymbolAddress((void**)&H,    g_H);
    cudaGetSymbolAddress((void**)&H1,   g_H1);
    cudaGetSymbolAddress((void**)&Q,    g_Q);
    cudaGetSymbolAddress((void**)&K,    g_K);
    cudaGetSymbolAddress((void**)&V,    g_V);
    cudaGetSymbolAddress((void**)&QR,   g_QR);
    cudaGetSymbolAddress((void**)&KR,   g_KR);
    cudaGetSymbolAddress((void**)&ATTN, g_ATTN);
    cudaGetSymbolAddress((void**)&MIXO, g_MIXO);
    cudaGetSymbolAddress((void**)&G,    g_G);
    cudaGetSymbolAddress((void**)&U,    g_U);

    cudaFuncSetAttribute(flash_kernel, cudaFuncAttributeMaxDynamicSharedMemorySize, FLASH_SMEM);

    const float scale = 0.08838834764831845f;

    for (int e = 0; e < 2; e++) {
        const float* w_ln  = (const float*)d_in[5 + e * 9 + 0];
        const float* wq    = (const float*)d_in[5 + e * 9 + 1];
        const float* wk    = (const float*)d_in[5 + e * 9 + 2];
        const float* wv    = (const float*)d_in[5 + e * 9 + 3];
        const float* wo    = (const float*)d_in[5 + e * 9 + 4];
        const float* w_pln = (const float*)d_in[5 + e * 9 + 5];
        const float* wg    = (const float*)d_in[5 + e * 9 + 6];
        const float* wu    = (const float*)d_in[5 + e * 9 + 7];
        const float* wd    = (const float*)d_in[5 + e * 9 + 8];

        float* Qe = Q + (long)e * S1 * HIDN;
        float* Ke = K + (long)e * S1 * HIDN;
        float* Ve = V + (long)e * S1 * HIDN;

        rmsnorm_kernel<<<S1, 256>>>(x[e], w_ln, H);

        gemm2(H, wq, Qe, nullptr, S1, HIDN, HIDN, HIDN, HIDN, HIDN, 0, 1.f);
        gemm2(H, wk, Ke, nullptr, S1, HIDN, HIDN, HIDN, HIDN, HIDN, 0, 1.f);
        gemm2(H, wv, Ve, nullptr, S1, HIDN, HIDN, HIDN, HIDN, HIDN, 0, 1.f);

        rope2_kernel<<<(S1 * NH * 64 + 255) / 256, 256>>>(Qe, QR, S1);
        rope2_kernel<<<(S1 * NH * 64 + 255) / 256, 256>>>(Ke, KR, S1);

        {
            dim3 grid(S1 / FA_BM, 1, NH);
            flash_kernel<<<grid, 256, FLASH_SMEM>>>(QR, KR, Ve, mask[e], ATTN, S1, scale);
        }

        gemm2(ATTN, wo, H1, x[e], S1, HIDN, HIDN, HIDN, HIDN, HIDN, HIDN, 1.f);

        rmsnorm_kernel<<<S1, 256>>>(H1, w_pln, H);

        gemm2(H, wg, G, nullptr, S1, INTER_, HIDN, HIDN, INTER_, INTER_, 0, 1.f);
        gemm2(H, wu, U, nullptr, S1, INTER_, HIDN, HIDN, INTER_, INTER_, 0, 1.f);
        gelumul2_kernel<<<(S1 * INTER_ + 255) / 256, 256>>>(G, U, S1 * INTER_);
        gemm2(G, wd, out + (long)e * S1 * HIDN, H1,
              S1, HIDN, INTER_, INTER_, HIDN, HIDN, HIDN, 1.f);
    }

    // ---- mix attention over concatenated pre-RoPE q/k/v ----
    {
        dim3 grid(S2 / FA_BM, 1, NH);
        flash_kernel<<<grid, 256, FLASH_SMEM>>>(Q, K, V, mixmask, ATTN, S2, scale);
    }

    for (int e = 0; e < 2; e++) {
        const float* wo = (const float*)d_in[5 + e * 9 + 4];
        float* oute = out + (long)e * S1 * HIDN;
        gemm2(ATTN + (long)e * S1 * HIDN, wo, MIXO, nullptr,
              S1, HIDN, HIDN, HIDN, HIDN, HIDN, 0, 1.f);
        add_kernel<<<(S1 * HIDN + 255) / 256, 256>>>(oute, MIXO, S1 * HIDN);
    }
}

// round 8
// speedup vs baseline: 1.4811x; 1.4811x over previous
#include <cuda_runtime.h>
#include <cuda_bf16.h>

#define S1   2048
#define S2   4096
#define HIDN 1024
#define NH   8
#define HD   128
#define INTER_ 4096

// ---------------- scratch ----------------
__device__ float g_H [S1 * HIDN];
__device__ float g_H1[S1 * HIDN];
__device__ float g_Q [S2 * HIDN];
__device__ float g_K [S2 * HIDN];
__device__ float g_V [S2 * HIDN];
__device__ float g_QR[S1 * HIDN];
__device__ float g_KR[S1 * HIDN];
__device__ float g_ATTN[S2 * HIDN];
__device__ float g_MIXO[S1 * HIDN];
__device__ float g_G[S1 * INTER_];
__device__ float g_U[S1 * INTER_];

// ---------------- NN GEMM: 128x128x16 tile, double-buffered, 8x8 micro ----------------
// C = alpha*A@B (+E).  A: MxK (lda), B: KxN (ldb), C: MxN (ldc).
// M%128==0, N%128==0, K%16==0 (true for all uses here).
template<bool HAS_E>
__global__ __launch_bounds__(256)
void gemm3_kernel(const float* __restrict__ A, const float* __restrict__ B,
                  float* __restrict__ C, const float* __restrict__ E,
                  int M, int N, int K, int lda, int ldb, int ldc, int lde, float alpha)
{
    __shared__ float As[2][16][132];   // [buf][k][m]
    __shared__ float Bs[2][16][132];   // [buf][k][n]

    const int bm = blockIdx.y * 128;
    const int bn = blockIdx.x * 128;
    const int tid = threadIdx.x;
    const int tx = tid & 15;           // 0..15 -> n block of 8
    const int ty = tid >> 4;           // 0..15 -> m block of 8

    // load mapping
    const int lr = tid >> 2;           // 0..63  A rows (two passes: +0, +64)
    const int lc = (tid & 3) * 4;      // 0,4,8,12  A k-cols
    const int br = tid >> 5;           // 0..7   B k-rows (two passes: +0, +8)
    const int bc = (tid & 31) * 4;     // 0..124 B n-cols

    float acc[8][8];
#pragma unroll
    for (int i = 0; i < 8; i++)
#pragma unroll
        for (int j = 0; j < 8; j++) acc[i][j] = 0.f;

    // prologue: tile 0 -> buf 0
#pragma unroll
    for (int p = 0; p < 2; p++) {
        float4 va = *(const float4*)(A + (long)(bm + lr + p * 64) * lda + lc);
        As[0][lc + 0][lr + p * 64] = va.x;
        As[0][lc + 1][lr + p * 64] = va.y;
        As[0][lc + 2][lr + p * 64] = va.z;
        As[0][lc + 3][lr + p * 64] = va.w;
        float4 vb = *(const float4*)(B + (long)(br + p * 8) * ldb + (bn + bc));
        *(float4*)&Bs[0][br + p * 8][bc] = vb;
    }
    __syncthreads();

    int cur = 0;
    for (int k0 = 0; k0 < K; k0 += 16) {
        float4 pa[2], pb[2];
        const bool has_next = (k0 + 16) < K;
        if (has_next) {
#pragma unroll
            for (int p = 0; p < 2; p++) {
                pa[p] = *(const float4*)(A + (long)(bm + lr + p * 64) * lda + (k0 + 16 + lc));
                pb[p] = *(const float4*)(B + (long)(k0 + 16 + br + p * 8) * ldb + (bn + bc));
            }
        }

#pragma unroll
        for (int kk = 0; kk < 16; kk++) {
            float4 a0 = *(const float4*)&As[cur][kk][ty * 8];
            float4 a1 = *(const float4*)&As[cur][kk][ty * 8 + 4];
            float4 b0 = *(const float4*)&Bs[cur][kk][tx * 8];
            float4 b1 = *(const float4*)&Bs[cur][kk][tx * 8 + 4];
            float a[8] = {a0.x, a0.y, a0.z, a0.w, a1.x, a1.y, a1.z, a1.w};
            float b[8] = {b0.x, b0.y, b0.z, b0.w, b1.x, b1.y, b1.z, b1.w};
#pragma unroll
            for (int i = 0; i < 8; i++)
#pragma unroll
                for (int j = 0; j < 8; j++)
                    acc[i][j] = fmaf(a[i], b[j], acc[i][j]);
        }

        if (has_next) {
            int nxt = cur ^ 1;
#pragma unroll
            for (int p = 0; p < 2; p++) {
                As[nxt][lc + 0][lr + p * 64] = pa[p].x;
                As[nxt][lc + 1][lr + p * 64] = pa[p].y;
                As[nxt][lc + 2][lr + p * 64] = pa[p].z;
                As[nxt][lc + 3][lr + p * 64] = pa[p].w;
                *(float4*)&Bs[nxt][br + p * 8][bc] = pb[p];
            }
            __syncthreads();
            cur = nxt;
        }
    }

    // epilogue (vectorized)
#pragma unroll
    for (int i = 0; i < 8; i++) {
        long row = bm + ty * 8 + i;
#pragma unroll
        for (int jv = 0; jv < 2; jv++) {
            int col = bn + tx * 8 + jv * 4;
            float4 v;
            v.x = alpha * acc[i][jv * 4 + 0];
            v.y = alpha * acc[i][jv * 4 + 1];
            v.z = alpha * acc[i][jv * 4 + 2];
            v.w = alpha * acc[i][jv * 4 + 3];
            if (HAS_E) {
                float4 ev = *(const float4*)(E + row * lde + col);
                v.x += ev.x; v.y += ev.y; v.z += ev.z; v.w += ev.w;
            }
            *(float4*)(C + row * ldc + col) = v;
        }
    }
}

// ---------------- flash attention (unchanged from passing R7) ----------------
#define FA_BM 64
#define FA_BN 64

__global__ __launch_bounds__(256)
void flash_kernel(const float* __restrict__ Qp, const float* __restrict__ Kp,
                  const float* __restrict__ Vp, const float* __restrict__ Mask,
                  float* __restrict__ Op, int L, float scale)
{
    extern __shared__ float sm[];
    float* Qs = sm;
    float* Ks = Qs + 128 * FA_BM;
    float* Vs = Ks + 128 * FA_BN;
    float* Ss = Vs + FA_BN * 128;
    float* mrow = Ss + FA_BM * 65;
    float* lrow = mrow + FA_BM;
    float* arow = lrow + FA_BM;

    const int h   = blockIdx.z;
    const int q0  = blockIdx.x * FA_BM;
    const int tid = threadIdx.x;
    const int tx  = tid & 15;
    const int ty  = tid >> 4;

    const float* Qh = Qp + h * HD;
    const float* Kh = Kp + h * HD;
    const float* Vh = Vp + h * HD;

    for (int i = tid; i < FA_BM * 32; i += 256) {
        int m = i >> 5, d4 = (i & 31) * 4;
        float4 v = *(const float4*)(Qh + (long)(q0 + m) * HIDN + d4);
        Qs[(d4 + 0) * FA_BM + m] = v.x;
        Qs[(d4 + 1) * FA_BM + m] = v.y;
        Qs[(d4 + 2) * FA_BM + m] = v.z;
        Qs[(d4 + 3) * FA_BM + m] = v.w;
    }
    if (tid < FA_BM) { mrow[tid] = -3.4e38f; lrow[tid] = 0.f; }

    float Oacc[4][8];
#pragma unroll
    for (int i = 0; i < 4; i++)
#pragma unroll
        for (int j = 0; j < 8; j++) Oacc[i][j] = 0.f;

    __syncthreads();

    for (int k0 = 0; k0 < L; k0 += FA_BN) {
        for (int i = tid; i < FA_BN * 32; i += 256) {
            int n = i >> 5, d4 = (i & 31) * 4;
            float4 kv = *(const float4*)(Kh + (long)(k0 + n) * HIDN + d4);
            Ks[(d4 + 0) * FA_BN + n] = kv.x;
            Ks[(d4 + 1) * FA_BN + n] = kv.y;
            Ks[(d4 + 2) * FA_BN + n] = kv.z;
            Ks[(d4 + 3) * FA_BN + n] = kv.w;
            float4 vv = *(const float4*)(Vh + (long)(k0 + n) * HIDN + d4);
            *(float4*)(Vs + n * 128 + d4) = vv;
        }
        __syncthreads();

        {
            float acc[4][4];
#pragma unroll
            for (int i = 0; i < 4; i++)
#pragma unroll
                for (int j = 0; j < 4; j++) acc[i][j] = 0.f;

            for (int d = 0; d < 128; d++) {
                float4 a4 = *(const float4*)(Qs + d * FA_BM + ty * 4);
                float4 b4 = *(const float4*)(Ks + d * FA_BN + tx * 4);
                float a[4] = {a4.x, a4.y, a4.z, a4.w};
                float b[4] = {b4.x, b4.y, b4.z, b4.w};
#pragma unroll
                for (int i = 0; i < 4; i++)
#pragma unroll
                    for (int j = 0; j < 4; j++)
                        acc[i][j] = fmaf(a[i], b[j], acc[i][j]);
            }
#pragma unroll
            for (int i = 0; i < 4; i++) {
                int row = q0 + ty * 4 + i;
#pragma unroll
                for (int j = 0; j < 4; j++) {
                    int col = k0 + tx * 4 + j;
                    Ss[(ty * 4 + i) * 65 + tx * 4 + j] =
                        acc[i][j] * scale + Mask[(long)row * L + col];
                }
            }
        }
        __syncthreads();

        if (tid < FA_BM) {
            float mold = mrow[tid];
            float mx = mold;
            for (int j = 0; j < FA_BN; j++) mx = fmaxf(mx, Ss[tid * 65 + j]);
            float alpha = expf(mold - mx);
            float sum = 0.f;
            for (int j = 0; j < FA_BN; j++) {
                float p = expf(Ss[tid * 65 + j] - mx);
                Ss[tid * 65 + j] = p;
                sum += p;
            }
            mrow[tid] = mx;
            lrow[tid] = lrow[tid] * alpha + sum;
            arow[tid] = alpha;
        }
        __syncthreads();

        {
            int oy = ty * 4;
#pragma unroll
            for (int i = 0; i < 4; i++) {
                float a = arow[oy + i];
#pragma unroll
                for (int j = 0; j < 8; j++) Oacc[i][j] *= a;
            }
            for (int n = 0; n < FA_BN; n++) {
                float p[4];
#pragma unroll
                for (int i = 0; i < 4; i++) p[i] = Ss[(oy + i) * 65 + n];
#pragma unroll
                for (int j = 0; j < 8; j++) {
                    float v = Vs[n * 128 + tx + 16 * j];
#pragma unroll
                    for (int i = 0; i < 4; i++)
                        Oacc[i][j] = fmaf(p[i], v, Oacc[i][j]);
                }
            }
        }
        __syncthreads();
    }

    int oy = ty * 4;
#pragma unroll
    for (int i = 0; i < 4; i++) {
        float inv = 1.f / lrow[oy + i];
#pragma unroll
        for (int j = 0; j < 8; j++)
            Op[(long)(q0 + oy + i) * HIDN + h * HD + tx + 16 * j] = Oacc[i][j] * inv;
    }
}
#define FLASH_SMEM ((128*FA_BM + 128*FA_BN + FA_BN*128 + FA_BM*65 + 3*FA_BM) * 4)

// ---------------- RMSNorm ----------------
__global__ __launch_bounds__(256)
void rmsnorm_kernel(const float* __restrict__ x, const float* __restrict__ w,
                    float* __restrict__ out)
{
    long row = blockIdx.x;
    const float* xr = x + row * HIDN;
    float* o = out + row * HIDN;
    int t = threadIdx.x;
    __shared__ float part[256];
    float ss = 0.f;
    for (int c = t; c < HIDN; c += 256) { float v = xr[c]; ss += v * v; }
    part[t] = ss; __syncthreads();
    for (int w2 = 128; w2 > 0; w2 >>= 1) {
        if (t < w2) part[t] += part[t + w2];
        __syncthreads();
    }
    float inv = rsqrtf(part[0] / (float)HIDN + 1e-6f);
    for (int c = t; c < HIDN; c += 256) o[c] = xr[c] * inv * (1.f + w[c]);
}

// ---------------- RoPE (accurate trig — DO NOT change; this was the R1-R6 bug) ------
__global__ __launch_bounds__(256)
void rope2_kernel(const float* __restrict__ in, float* __restrict__ out, int S)
{
    int idx = blockIdx.x * 256 + threadIdx.x;
    if (idx >= S * NH * 64) return;
    int d = idx & 63;
    int h = (idx >> 6) & 7;
    int s = idx >> 9;

    float inv = __powf(10000.0f, -((float)(2 * d)) / 128.0f);
    float ang = (float)s * inv;
    double cd, sd;
    sincos((double)ang, &sd, &cd);
    float c  = (float)cd;
    float sn = (float)sd;

    const float* ir = in + (long)s * HIDN + h * HD;
    float* orow = out + (long)s * HIDN + h * HD;
    float x0 = ir[d], x1 = ir[d + 64];
    orow[d]      = x0 * c - x1 * sn;
    orow[d + 64] = x1 * c + x0 * sn;
}

// ---------------- gelu(tanh)(g) * u in-place ----------------
__global__ __launch_bounds__(256)
void gelumul2_kernel(float* __restrict__ g, const float* __restrict__ u, int n)
{
    int i = blockIdx.x * 256 + threadIdx.x;
    if (i >= n) return;
    float x = g[i];
    float z = 0.7978845608028654f * (x + 0.044715f * x * x * x);
    float th = 1.f - 2.f / (expf(2.f * z) + 1.f);
    float t = 0.5f * x * (1.f + th);
    g[i] = t * u[i];
}

// ---------------- o[i] += a[i] ----------------
__global__ __launch_bounds__(256)
void add_kernel(float* __restrict__ o, const float* __restrict__ a, int n)
{
    int i = blockIdx.x * 256 + threadIdx.x;
    if (i < n) o[i] += a[i];
}

// ---------------- host helpers ----------------
static void gemm3(const float* A, const float* B, float* C, const float* E,
                  int M, int N, int K, int lda, int ldb, int ldc, int lde, float alpha)
{
    dim3 grid(N / 128, M / 128, 1);
    if (E) gemm3_kernel<true ><<<grid, 256>>>(A, B, C, E, M, N, K, lda, ldb, ldc, lde, alpha);
    else   gemm3_kernel<false><<<grid, 256>>>(A, B, C, E, M, N, K, lda, ldb, ldc, lde, alpha);
}

extern "C" void kernel_launch(void* const* d_in, const int* in_sizes, int n_in,
                              void* d_out, int out_size)
{
    (void)in_sizes; (void)n_in; (void)out_size;

    const float* x[2]    = { (const float*)d_in[0], (const float*)d_in[1] };
    const float* mask[2] = { (const float*)d_in[2], (const float*)d_in[3] };
    const float* mixmask = (const float*)d_in[4];
    float* out = (float*)d_out;

    float *H, *H1, *Q, *K, *V, *QR, *KR, *ATTN, *MIXO, *G, *U;
    cudaGetSymbolAddress((void**)&H,    g_H);
    cudaGetSymbolAddress((void**)&H1,   g_H1);
    cudaGetSymbolAddress((void**)&Q,    g_Q);
    cudaGetSymbolAddress((void**)&K,    g_K);
    cudaGetSymbolAddress((void**)&V,    g_V);
    cudaGetSymbolAddress((void**)&QR,   g_QR);
    cudaGetSymbolAddress((void**)&KR,   g_KR);
    cudaGetSymbolAddress((void**)&ATTN, g_ATTN);
    cudaGetSymbolAddress((void**)&MIXO, g_MIXO);
    cudaGetSymbolAddress((void**)&G,    g_G);
    cudaGetSymbolAddress((void**)&U,    g_U);

    cudaFuncSetAttribute(flash_kernel, cudaFuncAttributeMaxDynamicSharedMemorySize, FLASH_SMEM);

    const float scale = 0.08838834764831845f;

    for (int e = 0; e < 2; e++) {
        const float* w_ln  = (const float*)d_in[5 + e * 9 + 0];
        const float* wq    = (const float*)d_in[5 + e * 9 + 1];
        const float* wk    = (const float*)d_in[5 + e * 9 + 2];
        const float* wv    = (const float*)d_in[5 + e * 9 + 3];
        const float* wo    = (const float*)d_in[5 + e * 9 + 4];
        const float* w_pln = (const float*)d_in[5 + e * 9 + 5];
        const float* wg    = (const float*)d_in[5 + e * 9 + 6];
        const float* wu    = (const float*)d_in[5 + e * 9 + 7];
        const float* wd    = (const float*)d_in[5 + e * 9 + 8];

        float* Qe = Q + (long)e * S1 * HIDN;
        float* Ke = K + (long)e * S1 * HIDN;
        float* Ve = V + (long)e * S1 * HIDN;

        rmsnorm_kernel<<<S1, 256>>>(x[e], w_ln, H);

        gemm3(H, wq, Qe, nullptr, S1, HIDN, HIDN, HIDN, HIDN, HIDN, 0, 1.f);
        gemm3(H, wk, Ke, nullptr, S1, HIDN, HIDN, HIDN, HIDN, HIDN, 0, 1.f);
        gemm3(H, wv, Ve, nullptr, S1, HIDN, HIDN, HIDN, HIDN, HIDN, 0, 1.f);

        rope2_kernel<<<(S1 * NH * 64 + 255) / 256, 256>>>(Qe, QR, S1);
        rope2_kernel<<<(S1 * NH * 64 + 255) / 256, 256>>>(Ke, KR, S1);

        {
            dim3 grid(S1 / FA_BM, 1, NH);
            flash_kernel<<<grid, 256, FLASH_SMEM>>>(QR, KR, Ve, mask[e], ATTN, S1, scale);
        }

        gemm3(ATTN, wo, H1, x[e], S1, HIDN, HIDN, HIDN, HIDN, HIDN, HIDN, 1.f);

        rmsnorm_kernel<<<S1, 256>>>(H1, w_pln, H);

        gemm3(H, wg, G, nullptr, S1, INTER_, HIDN, HIDN, INTER_, INTER_, 0, 1.f);
        gemm3(H, wu, U, nullptr, S1, INTER_, HIDN, HIDN, INTER_, INTER_, 0, 1.f);
        gelumul2_kernel<<<(S1 * INTER_ + 255) / 256, 256>>>(G, U, S1 * INTER_);
        gemm3(G, wd, out + (long)e * S1 * HIDN, H1,
              S1, HIDN, INTER_, INTER_, HIDN, HIDN, HIDN, 1.f);
    }

    // ---- mix attention over concatenated pre-RoPE q/k/v ----
    {
        dim3 grid(S2 / FA_BM, 1, NH);
        flash_kernel<<<grid, 256, FLASH_SMEM>>>(Q, K, V, mixmask, ATTN, S2, scale);
    }

    for (int e = 0; e < 2; e++) {
        const float* wo = (const float*)d_in[5 + e * 9 + 4];
        float* oute = out + (long)e * S1 * HIDN;
        gemm3(ATTN + (long)e * S1 * HIDN, wo, MIXO, nullptr,
              S1, HIDN, HIDN, HIDN, HIDN, HIDN, 0, 1.f);
        add_kernel<<<(S1 * HIDN + 255) / 256, 256>>>(oute, MIXO, S1 * HIDN);
    }
}

// round 10
// speedup vs baseline: 1.9041x; 1.2857x over previous
#include <cuda_runtime.h>
#include <cuda_bf16.h>
#include <cstdint>

#define S1   2048
#define S2   4096
#define HIDN 1024
#define NH   8
#define HD   128
#define INTER_ 4096

// ---------------- scratch ----------------
__device__ float g_H [S1 * HIDN];
__device__ float g_H1[S1 * HIDN];
__device__ float g_Q [S2 * HIDN];
__device__ float g_K [S2 * HIDN];
__device__ float g_V [S2 * HIDN];
__device__ float g_QR[S1 * HIDN];
__device__ float g_KR[S1 * HIDN];
__device__ float g_ATTN[S2 * HIDN];
__device__ float g_MIXO[S1 * HIDN];
__device__ float g_G[S1 * INTER_];
__device__ float g_U[S1 * INTER_];

__device__ __forceinline__ uint32_t f2tf32(float f)
{
    uint32_t r;
    asm("cvt.rna.tf32.f32 %0, %1;" : "=r"(r) : "f"(f));
    return r;
}

// ---------------- TF32 tensor-core GEMM ----------------
// C = alpha*A@B (+E).  A: MxK row-major, B: KxN row-major.
// CTA tile 128x128, BK=16 double-buffered. 8 warps in 2(m)x4(n), warp tile 64x32.
// mma.sync.aligned.m16n8k8.row.col.f32.tf32.tf32.f32, fp32 accumulate.
// M%128==0, N%128==0, K%16==0.
template<bool HAS_E>
__global__ __launch_bounds__(256)
void gemm4_kernel(const float* __restrict__ A, const float* __restrict__ B,
                  float* __restrict__ C, const float* __restrict__ E,
                  int M, int N, int K, int lda, int ldb, int ldc, int lde, float alpha)
{
    __shared__ uint32_t As[2][16][136];   // [buf][k][m]  tf32 bits
    __shared__ uint32_t Bs[2][16][136];   // [buf][k][n]  tf32 bits

    const int bm = blockIdx.y * 128;
    const int bn = blockIdx.x * 128;
    const int tid  = threadIdx.x;
    const int wid  = tid >> 5;
    const int lane = tid & 31;
    const int wm = (wid & 1) * 64;        // warp m offset in tile
    const int wn = (wid >> 1) * 32;       // warp n offset in tile
    const int tg = lane >> 2;             // groupID 0..7
    const int tk = lane & 3;              // 0..3

    // load mapping (same as R8 gemm3)
    const int lr = tid >> 2;              // 0..63   A rows (passes +0,+64)
    const int lc = (tid & 3) * 4;         // 0,4,8,12  A k-cols
    const int br = tid >> 5;              // 0..7    B k-rows (passes +0,+8)
    const int bc = (tid & 31) * 4;        // 0..124  B n-cols

    float acc[4][4][4];                   // [mi][ni][reg]
#pragma unroll
    for (int mi = 0; mi < 4; mi++)
#pragma unroll
        for (int ni = 0; ni < 4; ni++)
#pragma unroll
            for (int r = 0; r < 4; r++) acc[mi][ni][r] = 0.f;

    // prologue: tile 0 -> buf 0
#pragma unroll
    for (int p = 0; p < 2; p++) {
        float4 va = *(const float4*)(A + (long)(bm + lr + p * 64) * lda + lc);
        As[0][lc + 0][lr + p * 64] = f2tf32(va.x);
        As[0][lc + 1][lr + p * 64] = f2tf32(va.y);
        As[0][lc + 2][lr + p * 64] = f2tf32(va.z);
        As[0][lc + 3][lr + p * 64] = f2tf32(va.w);
        float4 vb = *(const float4*)(B + (long)(br + p * 8) * ldb + (bn + bc));
        uint4 ub = { f2tf32(vb.x), f2tf32(vb.y), f2tf32(vb.z), f2tf32(vb.w) };
        *(uint4*)&Bs[0][br + p * 8][bc] = ub;
    }
    __syncthreads();

    int cur = 0;
    for (int k0 = 0; k0 < K; k0 += 16) {
        float4 pa[2], pb[2];
        const bool has_next = (k0 + 16) < K;
        if (has_next) {
#pragma unroll
            for (int p = 0; p < 2; p++) {
                pa[p] = *(const float4*)(A + (long)(bm + lr + p * 64) * lda + (k0 + 16 + lc));
                pb[p] = *(const float4*)(B + (long)(k0 + 16 + br + p * 8) * ldb + (bn + bc));
            }
        }

#pragma unroll
        for (int kc = 0; kc < 16; kc += 8) {
            // A fragments: a0=A[r][c], a1=A[r+8][c], a2=A[r][c+4], a3=A[r+8][c+4]
            uint32_t afr[4][4];
#pragma unroll
            for (int mi = 0; mi < 4; mi++) {
                int mb = wm + mi * 16 + tg;
                afr[mi][0] = As[cur][kc + tk    ][mb    ];
                afr[mi][1] = As[cur][kc + tk    ][mb + 8];
                afr[mi][2] = As[cur][kc + tk + 4][mb    ];
                afr[mi][3] = As[cur][kc + tk + 4][mb + 8];
            }
            // B fragments: b0=B[k][n], b1=B[k+4][n]
            uint32_t bfr[4][2];
#pragma unroll
            for (int ni = 0; ni < 4; ni++) {
                int nb = wn + ni * 8 + tg;
                bfr[ni][0] = Bs[cur][kc + tk    ][nb];
                bfr[ni][1] = Bs[cur][kc + tk + 4][nb];
            }
#pragma unroll
            for (int mi = 0; mi < 4; mi++)
#pragma unroll
                for (int ni = 0; ni < 4; ni++) {
                    asm volatile(
                        "mma.sync.aligned.m16n8k8.row.col.f32.tf32.tf32.f32 "
                        "{%0,%1,%2,%3}, {%4,%5,%6,%7}, {%8,%9}, {%0,%1,%2,%3};"
                        : "+f"(acc[mi][ni][0]), "+f"(acc[mi][ni][1]),
                          "+f"(acc[mi][ni][2]), "+f"(acc[mi][ni][3])
                        : "r"(afr[mi][0]), "r"(afr[mi][1]), "r"(afr[mi][2]), "r"(afr[mi][3]),
                          "r"(bfr[ni][0]), "r"(bfr[ni][1]));
                }
        }

        if (has_next) {
            int nxt = cur ^ 1;
#pragma unroll
            for (int p = 0; p < 2; p++) {
                As[nxt][lc + 0][lr + p * 64] = f2tf32(pa[p].x);
                As[nxt][lc + 1][lr + p * 64] = f2tf32(pa[p].y);
                As[nxt][lc + 2][lr + p * 64] = f2tf32(pa[p].z);
                As[nxt][lc + 3][lr + p * 64] = f2tf32(pa[p].w);
                uint4 ub = { f2tf32(pb[p].x), f2tf32(pb[p].y), f2tf32(pb[p].z), f2tf32(pb[p].w) };
                *(uint4*)&Bs[nxt][br + p * 8][bc] = ub;
            }
            __syncthreads();
            cur = nxt;
        }
    }

    // epilogue: c0=(r, 2tk), c1=(r, 2tk+1), c2=(r+8, 2tk), c3=(r+8, 2tk+1)
#pragma unroll
    for (int mi = 0; mi < 4; mi++) {
#pragma unroll
        for (int ni = 0; ni < 4; ni++) {
            long row0 = bm + wm + mi * 16 + tg;
            long row1 = row0 + 8;
            int col = bn + wn + ni * 8 + 2 * tk;
            float2 v0 = { alpha * acc[mi][ni][0], alpha * acc[mi][ni][1] };
            float2 v1 = { alpha * acc[mi][ni][2], alpha * acc[mi][ni][3] };
            if (HAS_E) {
                float2 e0 = *(const float2*)(E + row0 * lde + col);
                float2 e1 = *(const float2*)(E + row1 * lde + col);
                v0.x += e0.x; v0.y += e0.y;
                v1.x += e1.x; v1.y += e1.y;
            }
            *(float2*)(C + row0 * ldc + col) = v0;
            *(float2*)(C + row1 * ldc + col) = v1;
        }
    }
}

// ---------------- flash attention (unchanged from passing R8) ----------------
#define FA_BM 64
#define FA_BN 64

__global__ __launch_bounds__(256)
void flash_kernel(const float* __restrict__ Qp, const float* __restrict__ Kp,
                  const float* __restrict__ Vp, const float* __restrict__ Mask,
                  float* __restrict__ Op, int L, float scale)
{
    extern __shared__ float sm[];
    float* Qs = sm;
    float* Ks = Qs + 128 * FA_BM;
    float* Vs = Ks + 128 * FA_BN;
    float* Ss = Vs + FA_BN * 128;
    float* mrow = Ss + FA_BM * 65;
    float* lrow = mrow + FA_BM;
    float* arow = lrow + FA_BM;

    const int h   = blockIdx.z;
    const int q0  = blockIdx.x * FA_BM;
    const int tid = threadIdx.x;
    const int tx  = tid & 15;
    const int ty  = tid >> 4;

    const float* Qh = Qp + h * HD;
    const float* Kh = Kp + h * HD;
    const float* Vh = Vp + h * HD;

    for (int i = tid; i < FA_BM * 32; i += 256) {
        int m = i >> 5, d4 = (i & 31) * 4;
        float4 v = *(const float4*)(Qh + (long)(q0 + m) * HIDN + d4);
        Qs[(d4 + 0) * FA_BM + m] = v.x;
        Qs[(d4 + 1) * FA_BM + m] = v.y;
        Qs[(d4 + 2) * FA_BM + m] = v.z;
        Qs[(d4 + 3) * FA_BM + m] = v.w;
    }
    if (tid < FA_BM) { mrow[tid] = -3.4e38f; lrow[tid] = 0.f; }

    float Oacc[4][8];
#pragma unroll
    for (int i = 0; i < 4; i++)
#pragma unroll
        for (int j = 0; j < 8; j++) Oacc[i][j] = 0.f;

    __syncthreads();

    for (int k0 = 0; k0 < L; k0 += FA_BN) {
        for (int i = tid; i < FA_BN * 32; i += 256) {
            int n = i >> 5, d4 = (i & 31) * 4;
            float4 kv = *(const float4*)(Kh + (long)(k0 + n) * HIDN + d4);
            Ks[(d4 + 0) * FA_BN + n] = kv.x;
            Ks[(d4 + 1) * FA_BN + n] = kv.y;
            Ks[(d4 + 2) * FA_BN + n] = kv.z;
            Ks[(d4 + 3) * FA_BN + n] = kv.w;
            float4 vv = *(const float4*)(Vh + (long)(k0 + n) * HIDN + d4);
            *(float4*)(Vs + n * 128 + d4) = vv;
        }
        __syncthreads();

        {
            float acc[4][4];
#pragma unroll
            for (int i = 0; i < 4; i++)
#pragma unroll
                for (int j = 0; j < 4; j++) acc[i][j] = 0.f;

            for (int d = 0; d < 128; d++) {
                float4 a4 = *(const float4*)(Qs + d * FA_BM + ty * 4);
                float4 b4 = *(const float4*)(Ks + d * FA_BN + tx * 4);
                float a[4] = {a4.x, a4.y, a4.z, a4.w};
                float b[4] = {b4.x, b4.y, b4.z, b4.w};
#pragma unroll
                for (int i = 0; i < 4; i++)
#pragma unroll
                    for (int j = 0; j < 4; j++)
                        acc[i][j] = fmaf(a[i], b[j], acc[i][j]);
            }
#pragma unroll
            for (int i = 0; i < 4; i++) {
                int row = q0 + ty * 4 + i;
#pragma unroll
                for (int j = 0; j < 4; j++) {
                    int col = k0 + tx * 4 + j;
                    Ss[(ty * 4 + i) * 65 + tx * 4 + j] =
                        acc[i][j] * scale + Mask[(long)row * L + col];
                }
            }
        }
        __syncthreads();

        if (tid < FA_BM) {
            float mold = mrow[tid];
            float mx = mold;
            for (int j = 0; j < FA_BN; j++) mx = fmaxf(mx, Ss[tid * 65 + j]);
            float alpha = expf(mold - mx);
            float sum = 0.f;
            for (int j = 0; j < FA_BN; j++) {
                float p = expf(Ss[tid * 65 + j] - mx);
                Ss[tid * 65 + j] = p;
                sum += p;
            }
            mrow[tid] = mx;
            lrow[tid] = lrow[tid] * alpha + sum;
            arow[tid] = alpha;
        }
        __syncthreads();

        {
            int oy = ty * 4;
#pragma unroll
            for (int i = 0; i < 4; i++) {
                float a = arow[oy + i];
#pragma unroll
                for (int j = 0; j < 8; j++) Oacc[i][j] *= a;
            }
            for (int n = 0; n < FA_BN; n++) {
                float p[4];
#pragma unroll
                for (int i = 0; i < 4; i++) p[i] = Ss[(oy + i) * 65 + n];
#pragma unroll
                for (int j = 0; j < 8; j++) {
                    float v = Vs[n * 128 + tx + 16 * j];
#pragma unroll
                    for (int i = 0; i < 4; i++)
                        Oacc[i][j] = fmaf(p[i], v, Oacc[i][j]);
                }
            }
        }
        __syncthreads();
    }

    int oy = ty * 4;
#pragma unroll
    for (int i = 0; i < 4; i++) {
        float inv = 1.f / lrow[oy + i];
#pragma unroll
        for (int j = 0; j < 8; j++)
            Op[(long)(q0 + oy + i) * HIDN + h * HD + tx + 16 * j] = Oacc[i][j] * inv;
    }
}
#define FLASH_SMEM ((128*FA_BM + 128*FA_BN + FA_BN*128 + FA_BM*65 + 3*FA_BM) * 4)

// ---------------- RMSNorm ----------------
__global__ __launch_bounds__(256)
void rmsnorm_kernel(const float* __restrict__ x, const float* __restrict__ w,
                    float* __restrict__ out)
{
    long row = blockIdx.x;
    const float* xr = x + row * HIDN;
    float* o = out + row * HIDN;
    int t = threadIdx.x;
    __shared__ float part[256];
    float ss = 0.f;
    for (int c = t; c < HIDN; c += 256) { float v = xr[c]; ss += v * v; }
    part[t] = ss; __syncthreads();
    for (int w2 = 128; w2 > 0; w2 >>= 1) {
        if (t < w2) part[t] += part[t + w2];
        __syncthreads();
    }
    float inv = rsqrtf(part[0] / (float)HIDN + 1e-6f);
    for (int c = t; c < HIDN; c += 256) o[c] = xr[c] * inv * (1.f + w[c]);
}

// ---------------- RoPE (accurate trig — DO NOT change; this was the R1-R6 bug) ------
__global__ __launch_bounds__(256)
void rope2_kernel(const float* __restrict__ in, float* __restrict__ out, int S)
{
    int idx = blockIdx.x * 256 + threadIdx.x;
    if (idx >= S * NH * 64) return;
    int d = idx & 63;
    int h = (idx >> 6) & 7;
    int s = idx >> 9;

    float inv = __powf(10000.0f, -((float)(2 * d)) / 128.0f);
    float ang = (float)s * inv;
    double cd, sd;
    sincos((double)ang, &sd, &cd);
    float c  = (float)cd;
    float sn = (float)sd;

    const float* ir = in + (long)s * HIDN + h * HD;
    float* orow = out + (long)s * HIDN + h * HD;
    float x0 = ir[d], x1 = ir[d + 64];
    orow[d]      = x0 * c - x1 * sn;
    orow[d + 64] = x1 * c + x0 * sn;
}

// ---------------- gelu(tanh)(g) * u in-place ----------------
__global__ __launch_bounds__(256)
void gelumul2_kernel(float* __restrict__ g, const float* __restrict__ u, int n)
{
    int i = blockIdx.x * 256 + threadIdx.x;
    if (i >= n) return;
    float x = g[i];
    float z = 0.7978845608028654f * (x + 0.044715f * x * x * x);
    float th = 1.f - 2.f / (expf(2.f * z) + 1.f);
    float t = 0.5f * x * (1.f + th);
    g[i] = t * u[i];
}

// ---------------- o[i] += a[i] ----------------
__global__ __launch_bounds__(256)
void add_kernel(float* __restrict__ o, const float* __restrict__ a, int n)
{
    int i = blockIdx.x * 256 + threadIdx.x;
    if (i < n) o[i] += a[i];
}

// ---------------- host helpers ----------------
static void gemm4(const float* A, const float* B, float* C, const float* E,
                  int M, int N, int K, int lda, int ldb, int ldc, int lde, float alpha)
{
    dim3 grid(N / 128, M / 128, 1);
    if (E) gemm4_kernel<true ><<<grid, 256>>>(A, B, C, E, M, N, K, lda, ldb, ldc, lde, alpha);
    else   gemm4_kernel<false><<<grid, 256>>>(A, B, C, E, M, N, K, lda, ldb, ldc, lde, alpha);
}

extern "C" void kernel_launch(void* const* d_in, const int* in_sizes, int n_in,
                              void* d_out, int out_size)
{
    (void)in_sizes; (void)n_in; (void)out_size;

    const float* x[2]    = { (const float*)d_in[0], (const float*)d_in[1] };
    const float* mask[2] = { (const float*)d_in[2], (const float*)d_in[3] };
    const float* mixmask = (const float*)d_in[4];
    float* out = (float*)d_out;

    float *H, *H1, *Q, *K, *V, *QR, *KR, *ATTN, *MIXO, *G, *U;
    cudaGetSymbolAddress((void**)&H,    g_H);
    cudaGetSymbolAddress((void**)&H1,   g_H1);
    cudaGetSymbolAddress((void**)&Q,    g_Q);
    cudaGetSymbolAddress((void**)&K,    g_K);
    cudaGetSymbolAddress((void**)&V,    g_V);
    cudaGetSymbolAddress((void**)&QR,   g_QR);
    cudaGetSymbolAddress((void**)&KR,   g_KR);
    cudaGetSymbolAddress((void**)&ATTN, g_ATTN);
    cudaGetSymbolAddress((void**)&MIXO, g_MIXO);
    cudaGetSymbolAddress((void**)&G,    g_G);
    cudaGetSymbolAddress((void**)&U,    g_U);

    cudaFuncSetAttribute(flash_kernel, cudaFuncAttributeMaxDynamicSharedMemorySize, FLASH_SMEM);

    const float scale = 0.08838834764831845f;

    for (int e = 0; e < 2; e++) {
        const float* w_ln  = (const float*)d_in[5 + e * 9 + 0];
        const float* wq    = (const float*)d_in[5 + e * 9 + 1];
        const float* wk    = (const float*)d_in[5 + e * 9 + 2];
        const float* wv    = (const float*)d_in[5 + e * 9 + 3];
        const float* wo    = (const float*)d_in[5 + e * 9 + 4];
        const float* w_pln = (const float*)d_in[5 + e * 9 + 5];
        const float* wg    = (const float*)d_in[5 + e * 9 + 6];
        const float* wu    = (const float*)d_in[5 + e * 9 + 7];
        const float* wd    = (const float*)d_in[5 + e * 9 + 8];

        float* Qe = Q + (long)e * S1 * HIDN;
        float* Ke = K + (long)e * S1 * HIDN;
        float* Ve = V + (long)e * S1 * HIDN;

        rmsnorm_kernel<<<S1, 256>>>(x[e], w_ln, H);

        gemm4(H, wq, Qe, nullptr, S1, HIDN, HIDN, HIDN, HIDN, HIDN, 0, 1.f);
        gemm4(H, wk, Ke, nullptr, S1, HIDN, HIDN, HIDN, HIDN, HIDN, 0, 1.f);
        gemm4(H, wv, Ve, nullptr, S1, HIDN, HIDN, HIDN, HIDN, HIDN, 0, 1.f);

        rope2_kernel<<<(S1 * NH * 64 + 255) / 256, 256>>>(Qe, QR, S1);
        rope2_kernel<<<(S1 * NH * 64 + 255) / 256, 256>>>(Ke, KR, S1);

        {
            dim3 grid(S1 / FA_BM, 1, NH);
            flash_kernel<<<grid, 256, FLASH_SMEM>>>(QR, KR, Ve, mask[e], ATTN, S1, scale);
        }

        gemm4(ATTN, wo, H1, x[e], S1, HIDN, HIDN, HIDN, HIDN, HIDN, HIDN, 1.f);

        rmsnorm_kernel<<<S1, 256>>>(H1, w_pln, H);

        gemm4(H, wg, G, nullptr, S1, INTER_, HIDN, HIDN, INTER_, INTER_, 0, 1.f);
        gemm4(H, wu, U, nullptr, S1, INTER_, HIDN, HIDN, INTER_, INTER_, 0, 1.f);
        gelumul2_kernel<<<(S1 * INTER_ + 255) / 256, 256>>>(G, U, S1 * INTER_);
        gemm4(G, wd, out + (long)e * S1 * HIDN, H1,
              S1, HIDN, INTER_, INTER_, HIDN, HIDN, HIDN, 1.f);
    }

    // ---- mix attention over concatenated pre-RoPE q/k/v ----
    {
        dim3 grid(S2 / FA_BM, 1, NH);
        flash_kernel<<<grid, 256, FLASH_SMEM>>>(Q, K, V, mixmask, ATTN, S2, scale);
    }

    for (int e = 0; e < 2; e++) {
        const float* wo = (const float*)d_in[5 + e * 9 + 4];
        float* oute = out + (long)e * S1 * HIDN;
        gemm4(ATTN + (long)e * S1 * HIDN, wo, MIXO, nullptr,
              S1, HIDN, HIDN, HIDN, HIDN, HIDN, 0, 1.f);
        add_kernel<<<(S1 * HIDN + 255) / 256, 256>>>(oute, MIXO, S1 * HIDN);
    }
}

// round 11
// speedup vs baseline: 2.5090x; 1.3176x over previous
#include <cuda_runtime.h>
#include <cuda_bf16.h>
#include <cstdint>

#define S1   2048
#define S2   4096
#define HIDN 1024
#define NH   8
#define HD   128
#define INTER_ 4096

// ---------------- scratch ----------------
__device__ float g_H [S1 * HIDN];
__device__ float g_H1[S1 * HIDN];
__device__ float g_Q [S2 * HIDN];
__device__ float g_K [S2 * HIDN];
__device__ float g_V [S2 * HIDN];
__device__ float g_QR[S1 * HIDN];
__device__ float g_KR[S1 * HIDN];
__device__ float g_ATTN[S2 * HIDN];
__device__ float g_MIXO[S1 * HIDN];
__device__ float g_G[S1 * INTER_];
__device__ float g_U[S1 * INTER_];

__device__ __forceinline__ uint32_t f2tf32(float f)
{
    uint32_t r;
    asm("cvt.rna.tf32.f32 %0, %1;" : "=r"(r) : "f"(f));
    return r;
}

#define MMA_TF32(acc, a, b) \
    asm volatile( \
        "mma.sync.aligned.m16n8k8.row.col.f32.tf32.tf32.f32 " \
        "{%0,%1,%2,%3}, {%4,%5,%6,%7}, {%8,%9}, {%0,%1,%2,%3};" \
        : "+f"(acc[0]), "+f"(acc[1]), "+f"(acc[2]), "+f"(acc[3]) \
        : "r"(a[0]), "r"(a[1]), "r"(a[2]), "r"(a[3]), "r"(b[0]), "r"(b[1]))

// ---------------- TF32 tensor-core GEMM (unchanged from passing R10) ----------------
template<bool HAS_E>
__global__ __launch_bounds__(256)
void gemm4_kernel(const float* __restrict__ A, const float* __restrict__ B,
                  float* __restrict__ C, const float* __restrict__ E,
                  int M, int N, int K, int lda, int ldb, int ldc, int lde, float alpha)
{
    __shared__ uint32_t As[2][16][136];
    __shared__ uint32_t Bs[2][16][136];

    const int bm = blockIdx.y * 128;
    const int bn = blockIdx.x * 128;
    const int tid  = threadIdx.x;
    const int wid  = tid >> 5;
    const int lane = tid & 31;
    const int wm = (wid & 1) * 64;
    const int wn = (wid >> 1) * 32;
    const int tg = lane >> 2;
    const int tk = lane & 3;

    const int lr = tid >> 2;
    const int lc = (tid & 3) * 4;
    const int br = tid >> 5;
    const int bc = (tid & 31) * 4;

    float acc[4][4][4];
#pragma unroll
    for (int mi = 0; mi < 4; mi++)
#pragma unroll
        for (int ni = 0; ni < 4; ni++)
#pragma unroll
            for (int r = 0; r < 4; r++) acc[mi][ni][r] = 0.f;

#pragma unroll
    for (int p = 0; p < 2; p++) {
        float4 va = *(const float4*)(A + (long)(bm + lr + p * 64) * lda + lc);
        As[0][lc + 0][lr + p * 64] = f2tf32(va.x);
        As[0][lc + 1][lr + p * 64] = f2tf32(va.y);
        As[0][lc + 2][lr + p * 64] = f2tf32(va.z);
        As[0][lc + 3][lr + p * 64] = f2tf32(va.w);
        float4 vb = *(const float4*)(B + (long)(br + p * 8) * ldb + (bn + bc));
        uint4 ub = { f2tf32(vb.x), f2tf32(vb.y), f2tf32(vb.z), f2tf32(vb.w) };
        *(uint4*)&Bs[0][br + p * 8][bc] = ub;
    }
    __syncthreads();

    int cur = 0;
    for (int k0 = 0; k0 < K; k0 += 16) {
        float4 pa[2], pb[2];
        const bool has_next = (k0 + 16) < K;
        if (has_next) {
#pragma unroll
            for (int p = 0; p < 2; p++) {
                pa[p] = *(const float4*)(A + (long)(bm + lr + p * 64) * lda + (k0 + 16 + lc));
                pb[p] = *(const float4*)(B + (long)(k0 + 16 + br + p * 8) * ldb + (bn + bc));
            }
        }

#pragma unroll
        for (int kc = 0; kc < 16; kc += 8) {
            uint32_t afr[4][4];
#pragma unroll
            for (int mi = 0; mi < 4; mi++) {
                int mb = wm + mi * 16 + tg;
                afr[mi][0] = As[cur][kc + tk    ][mb    ];
                afr[mi][1] = As[cur][kc + tk    ][mb + 8];
                afr[mi][2] = As[cur][kc + tk + 4][mb    ];
                afr[mi][3] = As[cur][kc + tk + 4][mb + 8];
            }
            uint32_t bfr[4][2];
#pragma unroll
            for (int ni = 0; ni < 4; ni++) {
                int nb = wn + ni * 8 + tg;
                bfr[ni][0] = Bs[cur][kc + tk    ][nb];
                bfr[ni][1] = Bs[cur][kc + tk + 4][nb];
            }
#pragma unroll
            for (int mi = 0; mi < 4; mi++)
#pragma unroll
                for (int ni = 0; ni < 4; ni++)
                    MMA_TF32(acc[mi][ni], afr[mi], bfr[ni]);
        }

        if (has_next) {
            int nxt = cur ^ 1;
#pragma unroll
            for (int p = 0; p < 2; p++) {
                As[nxt][lc + 0][lr + p * 64] = f2tf32(pa[p].x);
                As[nxt][lc + 1][lr + p * 64] = f2tf32(pa[p].y);
                As[nxt][lc + 2][lr + p * 64] = f2tf32(pa[p].z);
                As[nxt][lc + 3][lr + p * 64] = f2tf32(pa[p].w);
                uint4 ub = { f2tf32(pb[p].x), f2tf32(pb[p].y), f2tf32(pb[p].z), f2tf32(pb[p].w) };
                *(uint4*)&Bs[nxt][br + p * 8][bc] = ub;
            }
            __syncthreads();
            cur = nxt;
        }
    }

#pragma unroll
    for (int mi = 0; mi < 4; mi++) {
#pragma unroll
        for (int ni = 0; ni < 4; ni++) {
            long row0 = bm + wm + mi * 16 + tg;
            long row1 = row0 + 8;
            int col = bn + wn + ni * 8 + 2 * tk;
            float2 v0 = { alpha * acc[mi][ni][0], alpha * acc[mi][ni][1] };
            float2 v1 = { alpha * acc[mi][ni][2], alpha * acc[mi][ni][3] };
            if (HAS_E) {
                float2 e0 = *(const float2*)(E + row0 * lde + col);
                float2 e1 = *(const float2*)(E + row1 * lde + col);
                v0.x += e0.x; v0.y += e0.y;
                v1.x += e1.x; v1.y += e1.y;
            }
            *(float2*)(C + row0 * ldc + col) = v0;
            *(float2*)(C + row1 * ldc + col) = v1;
        }
    }
}

// ---------------- tensor-core flash attention ----------------
// O[q0+m, h*HD+d] = softmax(scale*Q·K^T + Mask)·V, online softmax per 64-row tile.
// causal=1: skip fully-masked key tiles (k0 > q0 block) — exact (exp(-1e9)==0 in fp32).
#define TBM 64
#define TBN 64
#define SQ  72    // stride for Qs/Ks/Ps  (bank: tg + 8*tk -> conflict-free fragments)
#define SV  136   // stride for Vs

__global__ __launch_bounds__(256)
void flash_tc_kernel(const float* __restrict__ Qp, const float* __restrict__ Kp,
                     const float* __restrict__ Vp, const float* __restrict__ Mask,
                     float* __restrict__ Op, int L, float scale, int causal)
{
    extern __shared__ uint32_t smu[];
    uint32_t* Qs = smu;                 // [128][SQ]  tf32, [d][m]
    uint32_t* Ks = Qs + 128 * SQ;       // [128][SQ]  tf32, [d][n]
    uint32_t* Vs = Ks + 128 * SQ;       // [64][SV]   tf32, [n][d]
    uint32_t* Ps = Vs + TBN * SV;       // [64][SQ]   f32 scores -> tf32 probs, [n][m]
    float* arow = (float*)(Ps + TBM * SQ);  // [64]
    float* lrow = arow + 64;                // [64]

    const int h   = blockIdx.z;
    const int q0  = blockIdx.x * TBM;
    const int tid = threadIdx.x;
    const int wid = tid >> 5;
    const int lane = tid & 31;
    const int tg = lane >> 2;
    const int tk = lane & 3;
    const int wms = (wid & 1) * 32, wns = (wid >> 1) * 16;   // QK: 2m x 4n warps
    const int wmo = (wid & 1) * 32, wdo = (wid >> 1) * 32;   // PV: 2m x 4d warps

    const float* Qh = Qp + h * HD;
    const float* Kh = Kp + h * HD;
    const float* Vh = Vp + h * HD;

    // load Q tile -> Qs[d][m] (tf32)
    for (int i = tid; i < TBM * 32; i += 256) {
        int m = i >> 5, d4 = (i & 31) * 4;
        float4 v = *(const float4*)(Qh + (long)(q0 + m) * HIDN + d4);
        Qs[(d4 + 0) * SQ + m] = f2tf32(v.x);
        Qs[(d4 + 1) * SQ + m] = f2tf32(v.y);
        Qs[(d4 + 2) * SQ + m] = f2tf32(v.z);
        Qs[(d4 + 3) * SQ + m] = f2tf32(v.w);
    }

    float m_i = -3.4e38f, l_i = 0.f;    // live in threads tid<64 (row = tid)
    float Oacc[2][4][4];
#pragma unroll
    for (int mi = 0; mi < 2; mi++)
#pragma unroll
        for (int ni = 0; ni < 4; ni++)
#pragma unroll
            for (int r = 0; r < 4; r++) Oacc[mi][ni][r] = 0.f;

    __syncthreads();

    const int ktiles = causal ? (q0 / TBN + 1) : (L / TBN);
    for (int t = 0; t < ktiles; t++) {
        const int k0 = t * TBN;

        // load K -> Ks[d][n], V -> Vs[n][d] (tf32)
        for (int i = tid; i < TBN * 32; i += 256) {
            int n = i >> 5, d4 = (i & 31) * 4;
            float4 kv = *(const float4*)(Kh + (long)(k0 + n) * HIDN + d4);
            Ks[(d4 + 0) * SQ + n] = f2tf32(kv.x);
            Ks[(d4 + 1) * SQ + n] = f2tf32(kv.y);
            Ks[(d4 + 2) * SQ + n] = f2tf32(kv.z);
            Ks[(d4 + 3) * SQ + n] = f2tf32(kv.w);
            float4 vv = *(const float4*)(Vh + (long)(k0 + n) * HIDN + d4);
            uint4 uv = { f2tf32(vv.x), f2tf32(vv.y), f2tf32(vv.z), f2tf32(vv.w) };
            *(uint4*)(Vs + n * SV + d4) = uv;
        }
        __syncthreads();

        // ---- S = Q·K^T (warp tile 32x16) ----
        float sacc[2][2][4];
#pragma unroll
        for (int mi = 0; mi < 2; mi++)
#pragma unroll
            for (int ni = 0; ni < 2; ni++)
#pragma unroll
                for (int r = 0; r < 4; r++) sacc[mi][ni][r] = 0.f;

#pragma unroll
        for (int kc = 0; kc < 128; kc += 8) {
            uint32_t af[2][4], bf[2][2];
#pragma unroll
            for (int mi = 0; mi < 2; mi++) {
                int m = wms + mi * 16 + tg;
                af[mi][0] = Qs[(kc + tk    ) * SQ + m    ];
                af[mi][1] = Qs[(kc + tk    ) * SQ + m + 8];
                af[mi][2] = Qs[(kc + tk + 4) * SQ + m    ];
                af[mi][3] = Qs[(kc + tk + 4) * SQ + m + 8];
            }
#pragma unroll
            for (int ni = 0; ni < 2; ni++) {
                int n = wns + ni * 8 + tg;
                bf[ni][0] = Ks[(kc + tk    ) * SQ + n];
                bf[ni][1] = Ks[(kc + tk + 4) * SQ + n];
            }
#pragma unroll
            for (int mi = 0; mi < 2; mi++)
#pragma unroll
                for (int ni = 0; ni < 2; ni++)
                    MMA_TF32(sacc[mi][ni], af[mi], bf[ni]);
        }

        // scores*scale + mask -> Ps[n][m] (f32 bits)
#pragma unroll
        for (int mi = 0; mi < 2; mi++) {
#pragma unroll
            for (int ni = 0; ni < 2; ni++) {
                int m0 = wms + mi * 16 + tg;
                int n0 = wns + ni * 8 + 2 * tk;
                long grow0 = q0 + m0;
                long gcol  = k0 + n0;
                float2 mk0 = *(const float2*)(Mask + grow0 * L + gcol);
                float2 mk1 = *(const float2*)(Mask + (grow0 + 8) * L + gcol);
                Ps[(n0    ) * SQ + m0    ] = __float_as_uint(fmaf(sacc[mi][ni][0], scale, mk0.x));
                Ps[(n0 + 1) * SQ + m0    ] = __float_as_uint(fmaf(sacc[mi][ni][1], scale, mk0.y));
                Ps[(n0    ) * SQ + m0 + 8] = __float_as_uint(fmaf(sacc[mi][ni][2], scale, mk1.x));
                Ps[(n0 + 1) * SQ + m0 + 8] = __float_as_uint(fmaf(sacc[mi][ni][3], scale, mk1.y));
            }
        }
        __syncthreads();

        // ---- online softmax (thread tid handles row m=tid) ----
        if (tid < TBM) {
            float mx = m_i;
#pragma unroll 8
            for (int n = 0; n < TBN; n++)
                mx = fmaxf(mx, __uint_as_float(Ps[n * SQ + tid]));
            float al = expf(m_i - mx);
            float sum = 0.f;
#pragma unroll 8
            for (int n = 0; n < TBN; n++) {
                float p = expf(__uint_as_float(Ps[n * SQ + tid]) - mx);
                sum += p;
                Ps[n * SQ + tid] = f2tf32(p);
            }
            m_i = mx;
            l_i = l_i * al + sum;
            arow[tid] = al;
        }
        __syncthreads();

        // ---- O = O*alpha + P·V (warp tile 32x32, k = 64 keys) ----
#pragma unroll
        for (int mi = 0; mi < 2; mi++) {
            float al0 = arow[wmo + mi * 16 + tg];
            float al1 = arow[wmo + mi * 16 + tg + 8];
#pragma unroll
            for (int ni = 0; ni < 4; ni++) {
                Oacc[mi][ni][0] *= al0; Oacc[mi][ni][1] *= al0;
                Oacc[mi][ni][2] *= al1; Oacc[mi][ni][3] *= al1;
            }
        }
#pragma unroll
        for (int kc = 0; kc < TBN; kc += 8) {
            uint32_t af[2][4], bf[4][2];
#pragma unroll
            for (int mi = 0; mi < 2; mi++) {
                int m = wmo + mi * 16 + tg;
                af[mi][0] = Ps[(kc + tk    ) * SQ + m    ];
                af[mi][1] = Ps[(kc + tk    ) * SQ + m + 8];
                af[mi][2] = Ps[(kc + tk + 4) * SQ + m    ];
                af[mi][3] = Ps[(kc + tk + 4) * SQ + m + 8];
            }
#pragma unroll
            for (int ni = 0; ni < 4; ni++) {
                int d = wdo + ni * 8 + tg;
                bf[ni][0] = Vs[(kc + tk    ) * SV + d];
                bf[ni][1] = Vs[(kc + tk + 4) * SV + d];
            }
#pragma unroll
            for (int mi = 0; mi < 2; mi++)
#pragma unroll
                for (int ni = 0; ni < 4; ni++)
                    MMA_TF32(Oacc[mi][ni], af[mi], bf[ni]);
        }
        __syncthreads();
    }

    if (tid < TBM) lrow[tid] = l_i;
    __syncthreads();

    // epilogue
#pragma unroll
    for (int mi = 0; mi < 2; mi++) {
        int m0 = wmo + mi * 16 + tg;
        float inv0 = 1.f / lrow[m0];
        float inv1 = 1.f / lrow[m0 + 8];
#pragma unroll
        for (int ni = 0; ni < 4; ni++) {
            int d0 = wdo + ni * 8 + 2 * tk;
            float2 o0 = { Oacc[mi][ni][0] * inv0, Oacc[mi][ni][1] * inv0 };
            float2 o1 = { Oacc[mi][ni][2] * inv1, Oacc[mi][ni][3] * inv1 };
            *(float2*)(Op + (long)(q0 + m0    ) * HIDN + h * HD + d0) = o0;
            *(float2*)(Op + (long)(q0 + m0 + 8) * HIDN + h * HD + d0) = o1;
        }
    }
}
#define FLASH_TC_SMEM ((128*SQ + 128*SQ + TBN*SV + TBM*SQ) * 4 + 2 * 64 * 4)

// ---------------- RMSNorm ----------------
__global__ __launch_bounds__(256)
void rmsnorm_kernel(const float* __restrict__ x, const float* __restrict__ w,
                    float* __restrict__ out)
{
    long row = blockIdx.x;
    const float* xr = x + row * HIDN;
    float* o = out + row * HIDN;
    int t = threadIdx.x;
    __shared__ float part[256];
    float ss = 0.f;
    for (int c = t; c < HIDN; c += 256) { float v = xr[c]; ss += v * v; }
    part[t] = ss; __syncthreads();
    for (int w2 = 128; w2 > 0; w2 >>= 1) {
        if (t < w2) part[t] += part[t + w2];
        __syncthreads();
    }
    float inv = rsqrtf(part[0] / (float)HIDN + 1e-6f);
    for (int c = t; c < HIDN; c += 256) o[c] = xr[c] * inv * (1.f + w[c]);
}

// ---------------- RoPE (accurate trig — DO NOT change; this was the R1-R6 bug) ------
__global__ __launch_bounds__(256)
void rope2_kernel(const float* __restrict__ in, float* __restrict__ out, int S)
{
    int idx = blockIdx.x * 256 + threadIdx.x;
    if (idx >= S * NH * 64) return;
    int d = idx & 63;
    int h = (idx >> 6) & 7;
    int s = idx >> 9;

    float inv = __powf(10000.0f, -((float)(2 * d)) / 128.0f);
    float ang = (float)s * inv;
    double cd, sd;
    sincos((double)ang, &sd, &cd);
    float c  = (float)cd;
    float sn = (float)sd;

    const float* ir = in + (long)s * HIDN + h * HD;
    float* orow = out + (long)s * HIDN + h * HD;
    float x0 = ir[d], x1 = ir[d + 64];
    orow[d]      = x0 * c - x1 * sn;
    orow[d + 64] = x1 * c + x0 * sn;
}

// ---------------- gelu(tanh)(g) * u in-place ----------------
__global__ __launch_bounds__(256)
void gelumul2_kernel(float* __restrict__ g, const float* __restrict__ u, int n)
{
    int i = blockIdx.x * 256 + threadIdx.x;
    if (i >= n) return;
    float x = g[i];
    float z = 0.7978845608028654f * (x + 0.044715f * x * x * x);
    float th = 1.f - 2.f / (expf(2.f * z) + 1.f);
    float t = 0.5f * x * (1.f + th);
    g[i] = t * u[i];
}

// ---------------- o[i] += a[i] ----------------
__global__ __launch_bounds__(256)
void add_kernel(float* __restrict__ o, const float* __restrict__ a, int n)
{
    int i = blockIdx.x * 256 + threadIdx.x;
    if (i < n) o[i] += a[i];
}

// ---------------- host helpers ----------------
static void gemm4(const float* A, const float* B, float* C, const float* E,
                  int M, int N, int K, int lda, int ldb, int ldc, int lde, float alpha)
{
    dim3 grid(N / 128, M / 128, 1);
    if (E) gemm4_kernel<true ><<<grid, 256>>>(A, B, C, E, M, N, K, lda, ldb, ldc, lde, alpha);
    else   gemm4_kernel<false><<<grid, 256>>>(A, B, C, E, M, N, K, lda, ldb, ldc, lde, alpha);
}

extern "C" void kernel_launch(void* const* d_in, const int* in_sizes, int n_in,
                              void* d_out, int out_size)
{
    (void)in_sizes; (void)n_in; (void)out_size;

    const float* x[2]    = { (const float*)d_in[0], (const float*)d_in[1] };
    const float* mask[2] = { (const float*)d_in[2], (const float*)d_in[3] };
    const float* mixmask = (const float*)d_in[4];
    float* out = (float*)d_out;

    float *H, *H1, *Q, *K, *V, *QR, *KR, *ATTN, *MIXO, *G, *U;
    cudaGetSymbolAddress((void**)&H,    g_H);
    cudaGetSymbolAddress((void**)&H1,   g_H1);
    cudaGetSymbolAddress((void**)&Q,    g_Q);
    cudaGetSymbolAddress((void**)&K,    g_K);
    cudaGetSymbolAddress((void**)&V,    g_V);
    cudaGetSymbolAddress((void**)&QR,   g_QR);
    cudaGetSymbolAddress((void**)&KR,   g_KR);
    cudaGetSymbolAddress((void**)&ATTN, g_ATTN);
    cudaGetSymbolAddress((void**)&MIXO, g_MIXO);
    cudaGetSymbolAddress((void**)&G,    g_G);
    cudaGetSymbolAddress((void**)&U,    g_U);

    cudaFuncSetAttribute(flash_tc_kernel, cudaFuncAttributeMaxDynamicSharedMemorySize, FLASH_TC_SMEM);

    const float scale = 0.08838834764831845f;

    for (int e = 0; e < 2; e++) {
        const float* w_ln  = (const float*)d_in[5 + e * 9 + 0];
        const float* wq    = (const float*)d_in[5 + e * 9 + 1];
        const float* wk    = (const float*)d_in[5 + e * 9 + 2];
        const float* wv    = (const float*)d_in[5 + e * 9 + 3];
        const float* wo    = (const float*)d_in[5 + e * 9 + 4];
        const float* w_pln = (const float*)d_in[5 + e * 9 + 5];
        const float* wg    = (const float*)d_in[5 + e * 9 + 6];
        const float* wu    = (const float*)d_in[5 + e * 9 + 7];
        const float* wd    = (const float*)d_in[5 + e * 9 + 8];

        float* Qe = Q + (long)e * S1 * HIDN;
        float* Ke = K + (long)e * S1 * HIDN;
        float* Ve = V + (long)e * S1 * HIDN;

        rmsnorm_kernel<<<S1, 256>>>(x[e], w_ln, H);

        gemm4(H, wq, Qe, nullptr, S1, HIDN, HIDN, HIDN, HIDN, HIDN, 0, 1.f);
        gemm4(H, wk, Ke, nullptr, S1, HIDN, HIDN, HIDN, HIDN, HIDN, 0, 1.f);
        gemm4(H, wv, Ve, nullptr, S1, HIDN, HIDN, HIDN, HIDN, HIDN, 0, 1.f);

        rope2_kernel<<<(S1 * NH * 64 + 255) / 256, 256>>>(Qe, QR, S1);
        rope2_kernel<<<(S1 * NH * 64 + 255) / 256, 256>>>(Ke, KR, S1);

        {
            dim3 grid(S1 / TBM, 1, NH);
            flash_tc_kernel<<<grid, 256, FLASH_TC_SMEM>>>(QR, KR, Ve, mask[e], ATTN, S1, scale, 1);
        }

        gemm4(ATTN, wo, H1, x[e], S1, HIDN, HIDN, HIDN, HIDN, HIDN, HIDN, 1.f);

        rmsnorm_kernel<<<S1, 256>>>(H1, w_pln, H);

        gemm4(H, wg, G, nullptr, S1, INTER_, HIDN, HIDN, INTER_, INTER_, 0, 1.f);
        gemm4(H, wu, U, nullptr, S1, INTER_, HIDN, HIDN, INTER_, INTER_, 0, 1.f);
        gelumul2_kernel<<<(S1 * INTER_ + 255) / 256, 256>>>(G, U, S1 * INTER_);
        gemm4(G, wd, out + (long)e * S1 * HIDN, H1,
              S1, HIDN, INTER_, INTER_, HIDN, HIDN, HIDN, 1.f);
    }

    // ---- mix attention over concatenated pre-RoPE q/k/v ----
    {
        dim3 grid(S2 / TBM, 1, NH);
        flash_tc_kernel<<<grid, 256, FLASH_TC_SMEM>>>(Q, K, V, mixmask, ATTN, S2, scale, 0);
    }

    for (int e = 0; e < 2; e++) {
        const float* wo = (const float*)d_in[5 + e * 9 + 4];
        float* oute = out + (long)e * S1 * HIDN;
        gemm4(ATTN + (long)e * S1 * HIDN, wo, MIXO, nullptr,
              S1, HIDN, HIDN, HIDN, HIDN, HIDN, 0, 1.f);
        add_kernel<<<(S1 * HIDN + 255) / 256, 256>>>(oute, MIXO, S1 * HIDN);
    }
}

// round 12
// speedup vs baseline: 2.7041x; 1.0778x over previous
#include <cuda_runtime.h>
#include <cuda_bf16.h>
#include <cstdint>

#define S1   2048
#define S2   4096
#define HIDN 1024
#define NH   8
#define HD   128
#define INTER_ 4096

// ---------------- scratch ----------------
__device__ float g_H [S1 * HIDN];
__device__ float g_H1[S1 * HIDN];
__device__ float g_Q [S2 * HIDN];
__device__ float g_K [S2 * HIDN];
__device__ float g_V [S2 * HIDN];
__device__ float g_QR[S1 * HIDN];
__device__ float g_KR[S1 * HIDN];
__device__ float g_ATTN[S2 * HIDN];
__device__ float g_G[S1 * INTER_];
__device__ float g_U[S1 * INTER_];
__device__ float g_COS[S1 * 64];
__device__ float g_SIN[S1 * 64];

__device__ __forceinline__ uint32_t f2tf32(float f)
{
    uint32_t r;
    asm("cvt.rna.tf32.f32 %0, %1;" : "=r"(r) : "f"(f));
    return r;
}

#define MMA_TF32(acc, a, b) \
    asm volatile( \
        "mma.sync.aligned.m16n8k8.row.col.f32.tf32.tf32.f32 " \
        "{%0,%1,%2,%3}, {%4,%5,%6,%7}, {%8,%9}, {%0,%1,%2,%3};" \
        : "+f"(acc[0]), "+f"(acc[1]), "+f"(acc[2]), "+f"(acc[3]) \
        : "r"(a[0]), "r"(a[1]), "r"(a[2]), "r"(a[3]), "r"(b[0]), "r"(b[1]))

// ---------------- batched TF32 tensor-core GEMM ----------------
// Per z-slice: C = alpha*A@B (+E).  A shared across slices.
struct GBEnt { const float* B; float* C; const float* E; };
struct GB3   { GBEnt e[3]; };

template<bool HAS_E>
__global__ __launch_bounds__(256, 2)
void gemm4_kernel(const float* __restrict__ A, GB3 gb,
                  int M, int N, int K, int lda, int ldb, int ldc, int lde, float alpha)
{
    __shared__ uint32_t As[2][16][136];
    __shared__ uint32_t Bs[2][16][136];

    const float* __restrict__ B = gb.e[blockIdx.z].B;
    float* __restrict__ C       = gb.e[blockIdx.z].C;
    const float* __restrict__ E = gb.e[blockIdx.z].E;

    const int bm = blockIdx.y * 128;
    const int bn = blockIdx.x * 128;
    const int tid  = threadIdx.x;
    const int wid  = tid >> 5;
    const int lane = tid & 31;
    const int wm = (wid & 1) * 64;
    const int wn = (wid >> 1) * 32;
    const int tg = lane >> 2;
    const int tk = lane & 3;

    const int lr = tid >> 2;
    const int lc = (tid & 3) * 4;
    const int br = tid >> 5;
    const int bc = (tid & 31) * 4;

    float acc[4][4][4];
#pragma unroll
    for (int mi = 0; mi < 4; mi++)
#pragma unroll
        for (int ni = 0; ni < 4; ni++)
#pragma unroll
            for (int r = 0; r < 4; r++) acc[mi][ni][r] = 0.f;

#pragma unroll
    for (int p = 0; p < 2; p++) {
        float4 va = *(const float4*)(A + (long)(bm + lr + p * 64) * lda + lc);
        As[0][lc + 0][lr + p * 64] = f2tf32(va.x);
        As[0][lc + 1][lr + p * 64] = f2tf32(va.y);
        As[0][lc + 2][lr + p * 64] = f2tf32(va.z);
        As[0][lc + 3][lr + p * 64] = f2tf32(va.w);
        float4 vb = *(const float4*)(B + (long)(br + p * 8) * ldb + (bn + bc));
        uint4 ub = { f2tf32(vb.x), f2tf32(vb.y), f2tf32(vb.z), f2tf32(vb.w) };
        *(uint4*)&Bs[0][br + p * 8][bc] = ub;
    }
    __syncthreads();

    int cur = 0;
    for (int k0 = 0; k0 < K; k0 += 16) {
        float4 pa[2], pb[2];
        const bool has_next = (k0 + 16) < K;
        if (has_next) {
#pragma unroll
            for (int p = 0; p < 2; p++) {
                pa[p] = *(const float4*)(A + (long)(bm + lr + p * 64) * lda + (k0 + 16 + lc));
                pb[p] = *(const float4*)(B + (long)(k0 + 16 + br + p * 8) * ldb + (bn + bc));
            }
        }

#pragma unroll
        for (int kc = 0; kc < 16; kc += 8) {
            uint32_t afr[4][4];
#pragma unroll
            for (int mi = 0; mi < 4; mi++) {
                int mb = wm + mi * 16 + tg;
                afr[mi][0] = As[cur][kc + tk    ][mb    ];
                afr[mi][1] = As[cur][kc + tk    ][mb + 8];
                afr[mi][2] = As[cur][kc + tk + 4][mb    ];
                afr[mi][3] = As[cur][kc + tk + 4][mb + 8];
            }
            uint32_t bfr[4][2];
#pragma unroll
            for (int ni = 0; ni < 4; ni++) {
                int nb = wn + ni * 8 + tg;
                bfr[ni][0] = Bs[cur][kc + tk    ][nb];
                bfr[ni][1] = Bs[cur][kc + tk + 4][nb];
            }
#pragma unroll
            for (int mi = 0; mi < 4; mi++)
#pragma unroll
                for (int ni = 0; ni < 4; ni++)
                    MMA_TF32(acc[mi][ni], afr[mi], bfr[ni]);
        }

        if (has_next) {
            int nxt = cur ^ 1;
#pragma unroll
            for (int p = 0; p < 2; p++) {
                As[nxt][lc + 0][lr + p * 64] = f2tf32(pa[p].x);
                As[nxt][lc + 1][lr + p * 64] = f2tf32(pa[p].y);
                As[nxt][lc + 2][lr + p * 64] = f2tf32(pa[p].z);
                As[nxt][lc + 3][lr + p * 64] = f2tf32(pa[p].w);
                uint4 ub = { f2tf32(pb[p].x), f2tf32(pb[p].y), f2tf32(pb[p].z), f2tf32(pb[p].w) };
                *(uint4*)&Bs[nxt][br + p * 8][bc] = ub;
            }
            __syncthreads();
            cur = nxt;
        }
    }

#pragma unroll
    for (int mi = 0; mi < 4; mi++) {
#pragma unroll
        for (int ni = 0; ni < 4; ni++) {
            long row0 = bm + wm + mi * 16 + tg;
            long row1 = row0 + 8;
            int col = bn + wn + ni * 8 + 2 * tk;
            float2 v0 = { alpha * acc[mi][ni][0], alpha * acc[mi][ni][1] };
            float2 v1 = { alpha * acc[mi][ni][2], alpha * acc[mi][ni][3] };
            if (HAS_E) {
                float2 e0 = *(const float2*)(E + row0 * lde + col);
                float2 e1 = *(const float2*)(E + row1 * lde + col);
                v0.x += e0.x; v0.y += e0.y;
                v1.x += e1.x; v1.y += e1.y;
            }
            *(float2*)(C + row0 * ldc + col) = v0;
            *(float2*)(C + row1 * ldc + col) = v1;
        }
    }
}

// ---------------- tensor-core flash attention (unchanged from passing R11) ----------
#define TBM 64
#define TBN 64
#define SQ  72
#define SV  136

__global__ __launch_bounds__(256)
void flash_tc_kernel(const float* __restrict__ Qp, const float* __restrict__ Kp,
                     const float* __restrict__ Vp, const float* __restrict__ Mask,
                     float* __restrict__ Op, int L, float scale, int causal)
{
    extern __shared__ uint32_t smu[];
    uint32_t* Qs = smu;
    uint32_t* Ks = Qs + 128 * SQ;
    uint32_t* Vs = Ks + 128 * SQ;
    uint32_t* Ps = Vs + TBN * SV;
    float* arow = (float*)(Ps + TBM * SQ);
    float* lrow = arow + 64;

    const int h   = blockIdx.z;
    const int q0  = blockIdx.x * TBM;
    const int tid = threadIdx.x;
    const int wid = tid >> 5;
    const int lane = tid & 31;
    const int tg = lane >> 2;
    const int tk = lane & 3;
    const int wms = (wid & 1) * 32, wns = (wid >> 1) * 16;
    const int wmo = (wid & 1) * 32, wdo = (wid >> 1) * 32;

    const float* Qh = Qp + h * HD;
    const float* Kh = Kp + h * HD;
    const float* Vh = Vp + h * HD;

    for (int i = tid; i < TBM * 32; i += 256) {
        int m = i >> 5, d4 = (i & 31) * 4;
        float4 v = *(const float4*)(Qh + (long)(q0 + m) * HIDN + d4);
        Qs[(d4 + 0) * SQ + m] = f2tf32(v.x);
        Qs[(d4 + 1) * SQ + m] = f2tf32(v.y);
        Qs[(d4 + 2) * SQ + m] = f2tf32(v.z);
        Qs[(d4 + 3) * SQ + m] = f2tf32(v.w);
    }

    float m_i = -3.4e38f, l_i = 0.f;
    float Oacc[2][4][4];
#pragma unroll
    for (int mi = 0; mi < 2; mi++)
#pragma unroll
        for (int ni = 0; ni < 4; ni++)
#pragma unroll
            for (int r = 0; r < 4; r++) Oacc[mi][ni][r] = 0.f;

    __syncthreads();

    const int ktiles = causal ? (q0 / TBN + 1) : (L / TBN);
    for (int t = 0; t < ktiles; t++) {
        const int k0 = t * TBN;

        for (int i = tid; i < TBN * 32; i += 256) {
            int n = i >> 5, d4 = (i & 31) * 4;
            float4 kv = *(const float4*)(Kh + (long)(k0 + n) * HIDN + d4);
            Ks[(d4 + 0) * SQ + n] = f2tf32(kv.x);
            Ks[(d4 + 1) * SQ + n] = f2tf32(kv.y);
            Ks[(d4 + 2) * SQ + n] = f2tf32(kv.z);
            Ks[(d4 + 3) * SQ + n] = f2tf32(kv.w);
            float4 vv = *(const float4*)(Vh + (long)(k0 + n) * HIDN + d4);
            uint4 uv = { f2tf32(vv.x), f2tf32(vv.y), f2tf32(vv.z), f2tf32(vv.w) };
            *(uint4*)(Vs + n * SV + d4) = uv;
        }
        __syncthreads();

        float sacc[2][2][4];
#pragma unroll
        for (int mi = 0; mi < 2; mi++)
#pragma unroll
            for (int ni = 0; ni < 2; ni++)
#pragma unroll
                for (int r = 0; r < 4; r++) sacc[mi][ni][r] = 0.f;

#pragma unroll
        for (int kc = 0; kc < 128; kc += 8) {
            uint32_t af[2][4], bf[2][2];
#pragma unroll
            for (int mi = 0; mi < 2; mi++) {
                int m = wms + mi * 16 + tg;
                af[mi][0] = Qs[(kc + tk    ) * SQ + m    ];
                af[mi][1] = Qs[(kc + tk    ) * SQ + m + 8];
                af[mi][2] = Qs[(kc + tk + 4) * SQ + m    ];
                af[mi][3] = Qs[(kc + tk + 4) * SQ + m + 8];
            }
#pragma unroll
            for (int ni = 0; ni < 2; ni++) {
                int n = wns + ni * 8 + tg;
                bf[ni][0] = Ks[(kc + tk    ) * SQ + n];
                bf[ni][1] = Ks[(kc + tk + 4) * SQ + n];
            }
#pragma unroll
            for (int mi = 0; mi < 2; mi++)
#pragma unroll
                for (int ni = 0; ni < 2; ni++)
                    MMA_TF32(sacc[mi][ni], af[mi], bf[ni]);
        }

#pragma unroll
        for (int mi = 0; mi < 2; mi++) {
#pragma unroll
            for (int ni = 0; ni < 2; ni++) {
                int m0 = wms + mi * 16 + tg;
                int n0 = wns + ni * 8 + 2 * tk;
                long grow0 = q0 + m0;
                long gcol  = k0 + n0;
                float2 mk0 = *(const float2*)(Mask + grow0 * L + gcol);
                float2 mk1 = *(const float2*)(Mask + (grow0 + 8) * L + gcol);
                Ps[(n0    ) * SQ + m0    ] = __float_as_uint(fmaf(sacc[mi][ni][0], scale, mk0.x));
                Ps[(n0 + 1) * SQ + m0    ] = __float_as_uint(fmaf(sacc[mi][ni][1], scale, mk0.y));
                Ps[(n0    ) * SQ + m0 + 8] = __float_as_uint(fmaf(sacc[mi][ni][2], scale, mk1.x));
                Ps[(n0 + 1) * SQ + m0 + 8] = __float_as_uint(fmaf(sacc[mi][ni][3], scale, mk1.y));
            }
        }
        __syncthreads();

        if (tid < TBM) {
            float mx = m_i;
#pragma unroll 8
            for (int n = 0; n < TBN; n++)
                mx = fmaxf(mx, __uint_as_float(Ps[n * SQ + tid]));
            float al = expf(m_i - mx);
            float sum = 0.f;
#pragma unroll 8
            for (int n = 0; n < TBN; n++) {
                float p = expf(__uint_as_float(Ps[n * SQ + tid]) - mx);
                sum += p;
                Ps[n * SQ + tid] = f2tf32(p);
            }
            m_i = mx;
            l_i = l_i * al + sum;
            arow[tid] = al;
        }
        __syncthreads();

#pragma unroll
        for (int mi = 0; mi < 2; mi++) {
            float al0 = arow[wmo + mi * 16 + tg];
            float al1 = arow[wmo + mi * 16 + tg + 8];
#pragma unroll
            for (int ni = 0; ni < 4; ni++) {
                Oacc[mi][ni][0] *= al0; Oacc[mi][ni][1] *= al0;
                Oacc[mi][ni][2] *= al1; Oacc[mi][ni][3] *= al1;
            }
        }
#pragma unroll
        for (int kc = 0; kc < TBN; kc += 8) {
            uint32_t af[2][4], bf[4][2];
#pragma unroll
            for (int mi = 0; mi < 2; mi++) {
                int m = wmo + mi * 16 + tg;
                af[mi][0] = Ps[(kc + tk    ) * SQ + m    ];
                af[mi][1] = Ps[(kc + tk    ) * SQ + m + 8];
                af[mi][2] = Ps[(kc + tk + 4) * SQ + m    ];
                af[mi][3] = Ps[(kc + tk + 4) * SQ + m + 8];
            }
#pragma unroll
            for (int ni = 0; ni < 4; ni++) {
                int d = wdo + ni * 8 + tg;
                bf[ni][0] = Vs[(kc + tk    ) * SV + d];
                bf[ni][1] = Vs[(kc + tk + 4) * SV + d];
            }
#pragma unroll
            for (int mi = 0; mi < 2; mi++)
#pragma unroll
                for (int ni = 0; ni < 4; ni++)
                    MMA_TF32(Oacc[mi][ni], af[mi], bf[ni]);
        }
        __syncthreads();
    }

    if (tid < TBM) lrow[tid] = l_i;
    __syncthreads();

#pragma unroll
    for (int mi = 0; mi < 2; mi++) {
        int m0 = wmo + mi * 16 + tg;
        float inv0 = 1.f / lrow[m0];
        float inv1 = 1.f / lrow[m0 + 8];
#pragma unroll
        for (int ni = 0; ni < 4; ni++) {
            int d0 = wdo + ni * 8 + 2 * tk;
            float2 o0 = { Oacc[mi][ni][0] * inv0, Oacc[mi][ni][1] * inv0 };
            float2 o1 = { Oacc[mi][ni][2] * inv1, Oacc[mi][ni][3] * inv1 };
            *(float2*)(Op + (long)(q0 + m0    ) * HIDN + h * HD + d0) = o0;
            *(float2*)(Op + (long)(q0 + m0 + 8) * HIDN + h * HD + d0) = o1;
        }
    }
}
#define FLASH_TC_SMEM ((128*SQ + 128*SQ + TBN*SV + TBM*SQ) * 4 + 2 * 64 * 4)

// ---------------- RMSNorm ----------------
__global__ __launch_bounds__(256)
void rmsnorm_kernel(const float* __restrict__ x, const float* __restrict__ w,
                    float* __restrict__ out)
{
    long row = blockIdx.x;
    const float* xr = x + row * HIDN;
    float* o = out + row * HIDN;
    int t = threadIdx.x;
    __shared__ float part[256];
    float ss = 0.f;
    for (int c = t; c < HIDN; c += 256) { float v = xr[c]; ss += v * v; }
    part[t] = ss; __syncthreads();
    for (int w2 = 128; w2 > 0; w2 >>= 1) {
        if (t < w2) part[t] += part[t + w2];
        __syncthreads();
    }
    float inv = rsqrtf(part[0] / (float)HIDN + 1e-6f);
    for (int c = t; c < HIDN; c += 256) o[c] = xr[c] * inv * (1.f + w[c]);
}

// ---------------- RoPE table (accurate trig — semantics identical to the R7 fix) ----
__global__ __launch_bounds__(256)
void rope_table_kernel()
{
    int idx = blockIdx.x * 256 + threadIdx.x;
    if (idx >= S1 * 64) return;
    int d = idx & 63;
    int s = idx >> 6;
    float inv = __powf(10000.0f, -((float)(2 * d)) / 128.0f);
    float ang = (float)s * inv;
    double cd, sd;
    sincos((double)ang, &sd, &cd);
    g_COS[idx] = (float)cd;
    g_SIN[idx] = (float)sd;
}

__global__ __launch_bounds__(256)
void rope3_kernel(const float* __restrict__ in, float* __restrict__ out, int S)
{
    int idx = blockIdx.x * 256 + threadIdx.x;
    if (idx >= S * NH * 64) return;
    int d = idx & 63;
    int h = (idx >> 6) & 7;
    int s = idx >> 9;
    float c  = g_COS[s * 64 + d];
    float sn = g_SIN[s * 64 + d];
    const float* ir = in + (long)s * HIDN + h * HD;
    float* orow = out + (long)s * HIDN + h * HD;
    float x0 = ir[d], x1 = ir[d + 64];
    orow[d]      = x0 * c - x1 * sn;
    orow[d + 64] = x1 * c + x0 * sn;
}

// ---------------- gelu(tanh)(g) * u in-place ----------------
__global__ __launch_bounds__(256)
void gelumul2_kernel(float* __restrict__ g, const float* __restrict__ u, int n)
{
    int i = blockIdx.x * 256 + threadIdx.x;
    if (i >= n) return;
    float x = g[i];
    float z = 0.7978845608028654f * (x + 0.044715f * x * x * x);
    float th = 1.f - 2.f / (expf(2.f * z) + 1.f);
    float t = 0.5f * x * (1.f + th);
    g[i] = t * u[i];
}

// ---------------- host helpers ----------------
static void gemm_batch(const float* A, const GB3& gb, int nz, bool has_e,
                       int M, int N, int K, int lda, int ldb, int ldc, int lde, float alpha)
{
    dim3 grid(N / 128, M / 128, nz);
    if (has_e) gemm4_kernel<true ><<<grid, 256>>>(A, gb, M, N, K, lda, ldb, ldc, lde, alpha);
    else       gemm4_kernel<false><<<grid, 256>>>(A, gb, M, N, K, lda, ldb, ldc, lde, alpha);
}

static void gemm1(const float* A, const float* B, float* C, const float* E, bool has_e,
                  int M, int N, int K, int lda, int ldb, int ldc, int lde, float alpha)
{
    GB3 gb{}; gb.e[0] = { B, C, E };
    gemm_batch(A, gb, 1, has_e, M, N, K, lda, ldb, ldc, lde, alpha);
}

extern "C" void kernel_launch(void* const* d_in, const int* in_sizes, int n_in,
                              void* d_out, int out_size)
{
    (void)in_sizes; (void)n_in; (void)out_size;

    const float* x[2]    = { (const float*)d_in[0], (const float*)d_in[1] };
    const float* mask[2] = { (const float*)d_in[2], (const float*)d_in[3] };
    const float* mixmask = (const float*)d_in[4];
    float* out = (float*)d_out;

    float *H, *H1, *Q, *K, *V, *QR, *KR, *ATTN, *G, *U;
    cudaGetSymbolAddress((void**)&H,    g_H);
    cudaGetSymbolAddress((void**)&H1,   g_H1);
    cudaGetSymbolAddress((void**)&Q,    g_Q);
    cudaGetSymbolAddress((void**)&K,    g_K);
    cudaGetSymbolAddress((void**)&V,    g_V);
    cudaGetSymbolAddress((void**)&QR,   g_QR);
    cudaGetSymbolAddress((void**)&KR,   g_KR);
    cudaGetSymbolAddress((void**)&ATTN, g_ATTN);
    cudaGetSymbolAddress((void**)&G,    g_G);
    cudaGetSymbolAddress((void**)&U,    g_U);

    cudaFuncSetAttribute(flash_tc_kernel, cudaFuncAttributeMaxDynamicSharedMemorySize, FLASH_TC_SMEM);

    const float scale = 0.08838834764831845f;

    // cos/sin table (deterministic; re-run every replay)
    rope_table_kernel<<<(S1 * 64 + 255) / 256, 256>>>();

    for (int e = 0; e < 2; e++) {
        const float* w_ln  = (const float*)d_in[5 + e * 9 + 0];
        const float* wq    = (const float*)d_in[5 + e * 9 + 1];
        const float* wk    = (const float*)d_in[5 + e * 9 + 2];
        const float* wv    = (const float*)d_in[5 + e * 9 + 3];
        const float* wo    = (const float*)d_in[5 + e * 9 + 4];
        const float* w_pln = (const float*)d_in[5 + e * 9 + 5];
        const float* wg    = (const float*)d_in[5 + e * 9 + 6];
        const float* wu    = (const float*)d_in[5 + e * 9 + 7];
        const float* wd    = (const float*)d_in[5 + e * 9 + 8];

        float* Qe = Q + (long)e * S1 * HIDN;
        float* Ke = K + (long)e * S1 * HIDN;
        float* Ve = V + (long)e * S1 * HIDN;

        rmsnorm_kernel<<<S1, 256>>>(x[e], w_ln, H);

        // q/k/v in one batched launch (384 CTAs)
        {
            GB3 gb{};
            gb.e[0] = { wq, Qe, nullptr };
            gb.e[1] = { wk, Ke, nullptr };
            gb.e[2] = { wv, Ve, nullptr };
            gemm_batch(H, gb, 3, false, S1, HIDN, HIDN, HIDN, HIDN, HIDN, 0, 1.f);
        }

        rope3_kernel<<<(S1 * NH * 64 + 255) / 256, 256>>>(Qe, QR, S1);
        rope3_kernel<<<(S1 * NH * 64 + 255) / 256, 256>>>(Ke, KR, S1);

        {
            dim3 grid(S1 / TBM, 1, NH);
            flash_tc_kernel<<<grid, 256, FLASH_TC_SMEM>>>(QR, KR, Ve, mask[e], ATTN, S1, scale, 1);
        }

        gemm1(ATTN, wo, H1, x[e], true, S1, HIDN, HIDN, HIDN, HIDN, HIDN, HIDN, 1.f);

        rmsnorm_kernel<<<S1, 256>>>(H1, w_pln, H);

        // gate + up in one batched launch (1024 CTAs)
        {
            GB3 gb{};
            gb.e[0] = { wg, G, nullptr };
            gb.e[1] = { wu, U, nullptr };
            gemm_batch(H, gb, 2, false, S1, INTER_, HIDN, HIDN, INTER_, INTER_, 0, 1.f);
        }
        gelumul2_kernel<<<(S1 * INTER_ + 255) / 256, 256>>>(G, U, S1 * INTER_);
        gemm1(G, wd, out + (long)e * S1 * HIDN, H1, true,
              S1, HIDN, INTER_, INTER_, HIDN, HIDN, HIDN, 1.f);
    }

    // ---- mix attention over concatenated pre-RoPE q/k/v ----
    {
        dim3 grid(S2 / TBM, 1, NH);
        flash_tc_kernel<<<grid, 256, FLASH_TC_SMEM>>>(Q, K, V, mixmask, ATTN, S2, scale, 0);
    }

    // out[e] += mixed[e] @ wo_e  — fused epilogue (C == E elementwise, safe), batched z=2.
    // NOTE: A differs per slice, but A offset is uniform? No — pass per-slice A via B trick:
    // A must be shared; instead launch per-expert (A = ATTN slice differs). Two launches.
    for (int e = 0; e < 2; e++) {
        const float* wo = (const float*)d_in[5 + e * 9 + 4];
        float* oute = out + (long)e * S1 * HIDN;
        gemm1(ATTN + (long)e * S1 * HIDN, wo, oute, oute, true,
              S1, HIDN, HIDN, HIDN, HIDN, HIDN, HIDN, 1.f);
    }
}

// round 13
// speedup vs baseline: 2.8964x; 1.0711x over previous
#include <cuda_runtime.h>
#include <cuda_bf16.h>
#include <cstdint>

#define S1   2048
#define S2   4096
#define HIDN 1024
#define NH   8
#define HD   128
#define INTER_ 4096

// ---------------- scratch ----------------
__device__ float g_H [S1 * HIDN];
__device__ float g_H1[S1 * HIDN];
__device__ float g_Q [S2 * HIDN];
__device__ float g_K [S2 * HIDN];
__device__ float g_V [S2 * HIDN];
__device__ float g_QR[S1 * HIDN];
__device__ float g_KR[S1 * HIDN];
__device__ float g_ATTN[S2 * HIDN];
__device__ float g_G[S1 * INTER_];
__device__ float g_U[S1 * INTER_];
__device__ float g_COS[S1 * 64];
__device__ float g_SIN[S1 * 64];

__device__ __forceinline__ uint32_t f2tf32(float f)
{
    uint32_t r;
    asm("cvt.rna.tf32.f32 %0, %1;" : "=r"(r) : "f"(f));
    return r;
}

#define MMA_TF32(acc, a, b) \
    asm volatile( \
        "mma.sync.aligned.m16n8k8.row.col.f32.tf32.tf32.f32 " \
        "{%0,%1,%2,%3}, {%4,%5,%6,%7}, {%8,%9}, {%0,%1,%2,%3};" \
        : "+f"(acc[0]), "+f"(acc[1]), "+f"(acc[2]), "+f"(acc[3]) \
        : "r"(a[0]), "r"(a[1]), "r"(a[2]), "r"(a[3]), "r"(b[0]), "r"(b[1]))

// ---------------- batched TF32 tensor-core GEMM ----------------
// Per z-slice: C = alpha*A@B (+E).
struct GBEnt { const float* A; const float* B; float* C; const float* E; };
struct GB3   { GBEnt e[3]; };

template<bool HAS_E>
__global__ __launch_bounds__(256, 2)
void gemm4_kernel(GB3 gb,
                  int M, int N, int K, int lda, int ldb, int ldc, int lde, float alpha)
{
    __shared__ uint32_t As[2][16][136];
    __shared__ uint32_t Bs[2][16][136];

    const float* __restrict__ A = gb.e[blockIdx.z].A;
    const float* __restrict__ B = gb.e[blockIdx.z].B;
    float* __restrict__ C       = gb.e[blockIdx.z].C;
    const float* __restrict__ E = gb.e[blockIdx.z].E;

    const int bm = blockIdx.y * 128;
    const int bn = blockIdx.x * 128;
    const int tid  = threadIdx.x;
    const int wid  = tid >> 5;
    const int lane = tid & 31;
    const int wm = (wid & 1) * 64;
    const int wn = (wid >> 1) * 32;
    const int tg = lane >> 2;
    const int tk = lane & 3;

    const int lr = tid >> 2;
    const int lc = (tid & 3) * 4;
    const int br = tid >> 5;
    const int bc = (tid & 31) * 4;

    float acc[4][4][4];
#pragma unroll
    for (int mi = 0; mi < 4; mi++)
#pragma unroll
        for (int ni = 0; ni < 4; ni++)
#pragma unroll
            for (int r = 0; r < 4; r++) acc[mi][ni][r] = 0.f;

#pragma unroll
    for (int p = 0; p < 2; p++) {
        float4 va = *(const float4*)(A + (long)(bm + lr + p * 64) * lda + lc);
        As[0][lc + 0][lr + p * 64] = f2tf32(va.x);
        As[0][lc + 1][lr + p * 64] = f2tf32(va.y);
        As[0][lc + 2][lr + p * 64] = f2tf32(va.z);
        As[0][lc + 3][lr + p * 64] = f2tf32(va.w);
        float4 vb = *(const float4*)(B + (long)(br + p * 8) * ldb + (bn + bc));
        uint4 ub = { f2tf32(vb.x), f2tf32(vb.y), f2tf32(vb.z), f2tf32(vb.w) };
        *(uint4*)&Bs[0][br + p * 8][bc] = ub;
    }
    __syncthreads();

    int cur = 0;
    for (int k0 = 0; k0 < K; k0 += 16) {
        float4 pa[2], pb[2];
        const bool has_next = (k0 + 16) < K;
        if (has_next) {
#pragma unroll
            for (int p = 0; p < 2; p++) {
                pa[p] = *(const float4*)(A + (long)(bm + lr + p * 64) * lda + (k0 + 16 + lc));
                pb[p] = *(const float4*)(B + (long)(k0 + 16 + br + p * 8) * ldb + (bn + bc));
            }
        }

#pragma unroll
        for (int kc = 0; kc < 16; kc += 8) {
            uint32_t afr[4][4];
#pragma unroll
            for (int mi = 0; mi < 4; mi++) {
                int mb = wm + mi * 16 + tg;
                afr[mi][0] = As[cur][kc + tk    ][mb    ];
                afr[mi][1] = As[cur][kc + tk    ][mb + 8];
                afr[mi][2] = As[cur][kc + tk + 4][mb    ];
                afr[mi][3] = As[cur][kc + tk + 4][mb + 8];
            }
            uint32_t bfr[4][2];
#pragma unroll
            for (int ni = 0; ni < 4; ni++) {
                int nb = wn + ni * 8 + tg;
                bfr[ni][0] = Bs[cur][kc + tk    ][nb];
                bfr[ni][1] = Bs[cur][kc + tk + 4][nb];
            }
#pragma unroll
            for (int mi = 0; mi < 4; mi++)
#pragma unroll
                for (int ni = 0; ni < 4; ni++)
                    MMA_TF32(acc[mi][ni], afr[mi], bfr[ni]);
        }

        if (has_next) {
            int nxt = cur ^ 1;
#pragma unroll
            for (int p = 0; p < 2; p++) {
                As[nxt][lc + 0][lr + p * 64] = f2tf32(pa[p].x);
                As[nxt][lc + 1][lr + p * 64] = f2tf32(pa[p].y);
                As[nxt][lc + 2][lr + p * 64] = f2tf32(pa[p].z);
                As[nxt][lc + 3][lr + p * 64] = f2tf32(pa[p].w);
                uint4 ub = { f2tf32(pb[p].x), f2tf32(pb[p].y), f2tf32(pb[p].z), f2tf32(pb[p].w) };
                *(uint4*)&Bs[nxt][br + p * 8][bc] = ub;
            }
            __syncthreads();
            cur = nxt;
        }
    }

#pragma unroll
    for (int mi = 0; mi < 4; mi++) {
#pragma unroll
        for (int ni = 0; ni < 4; ni++) {
            long row0 = bm + wm + mi * 16 + tg;
            long row1 = row0 + 8;
            int col = bn + wn + ni * 8 + 2 * tk;
            float2 v0 = { alpha * acc[mi][ni][0], alpha * acc[mi][ni][1] };
            float2 v1 = { alpha * acc[mi][ni][2], alpha * acc[mi][ni][3] };
            if (HAS_E) {
                float2 e0 = *(const float2*)(E + row0 * lde + col);
                float2 e1 = *(const float2*)(E + row1 * lde + col);
                v0.x += e0.x; v0.y += e0.y;
                v1.x += e1.x; v1.y += e1.y;
            }
            *(float2*)(C + row0 * ldc + col) = v0;
            *(float2*)(C + row1 * ldc + col) = v1;
        }
    }
}

// ---------------- tensor-core flash attention, parallel softmax ----------------
#define TBM 64
#define TBN 64
#define SQ  72
#define SV  136

__global__ __launch_bounds__(256)
void flash_tc_kernel(const float* __restrict__ Qp, const float* __restrict__ Kp,
                     const float* __restrict__ Vp, const float* __restrict__ Mask,
                     float* __restrict__ Op, int L, float scale, int causal)
{
    extern __shared__ uint32_t smu[];
    uint32_t* Qs = smu;
    uint32_t* Ks = Qs + 128 * SQ;
    uint32_t* Vs = Ks + 128 * SQ;
    uint32_t* Ps = Vs + TBN * SV;
    float* arow = (float*)(Ps + TBM * SQ);
    float* lrow = arow + 64;

    const int h   = blockIdx.z;
    const int q0  = blockIdx.x * TBM;
    const int tid = threadIdx.x;
    const int wid = tid >> 5;
    const int lane = tid & 31;
    const int tg = lane >> 2;
    const int tk = lane & 3;
    const int wms = (wid & 1) * 32, wns = (wid >> 1) * 16;
    const int wmo = (wid & 1) * 32, wdo = (wid >> 1) * 32;
    const int srow = tid >> 2;          // softmax row 0..63 (4 lanes/row, same warp)
    const int spart = tid & 3;          // lane's column group

    const float* Qh = Qp + h * HD;
    const float* Kh = Kp + h * HD;
    const float* Vh = Vp + h * HD;

    for (int i = tid; i < TBM * 32; i += 256) {
        int m = i >> 5, d4 = (i & 31) * 4;
        float4 v = *(const float4*)(Qh + (long)(q0 + m) * HIDN + d4);
        Qs[(d4 + 0) * SQ + m] = f2tf32(v.x);
        Qs[(d4 + 1) * SQ + m] = f2tf32(v.y);
        Qs[(d4 + 2) * SQ + m] = f2tf32(v.z);
        Qs[(d4 + 3) * SQ + m] = f2tf32(v.w);
    }

    float m_i = -3.4e38f, l_i = 0.f;    // replicated across the 4 lanes of each row
    float Oacc[2][4][4];
#pragma unroll
    for (int mi = 0; mi < 2; mi++)
#pragma unroll
        for (int ni = 0; ni < 4; ni++)
#pragma unroll
            for (int r = 0; r < 4; r++) Oacc[mi][ni][r] = 0.f;

    __syncthreads();

    const int ktiles = causal ? (q0 / TBN + 1) : (L / TBN);
    for (int t = 0; t < ktiles; t++) {
        const int k0 = t * TBN;

        for (int i = tid; i < TBN * 32; i += 256) {
            int n = i >> 5, d4 = (i & 31) * 4;
            float4 kv = *(const float4*)(Kh + (long)(k0 + n) * HIDN + d4);
            Ks[(d4 + 0) * SQ + n] = f2tf32(kv.x);
            Ks[(d4 + 1) * SQ + n] = f2tf32(kv.y);
            Ks[(d4 + 2) * SQ + n] = f2tf32(kv.z);
            Ks[(d4 + 3) * SQ + n] = f2tf32(kv.w);
            float4 vv = *(const float4*)(Vh + (long)(k0 + n) * HIDN + d4);
            uint4 uv = { f2tf32(vv.x), f2tf32(vv.y), f2tf32(vv.z), f2tf32(vv.w) };
            *(uint4*)(Vs + n * SV + d4) = uv;
        }
        __syncthreads();

        float sacc[2][2][4];
#pragma unroll
        for (int mi = 0; mi < 2; mi++)
#pragma unroll
            for (int ni = 0; ni < 2; ni++)
#pragma unroll
                for (int r = 0; r < 4; r++) sacc[mi][ni][r] = 0.f;

#pragma unroll
        for (int kc = 0; kc < 128; kc += 8) {
            uint32_t af[2][4], bf[2][2];
#pragma unroll
            for (int mi = 0; mi < 2; mi++) {
                int m = wms + mi * 16 + tg;
                af[mi][0] = Qs[(kc + tk    ) * SQ + m    ];
                af[mi][1] = Qs[(kc + tk    ) * SQ + m + 8];
                af[mi][2] = Qs[(kc + tk + 4) * SQ + m    ];
                af[mi][3] = Qs[(kc + tk + 4) * SQ + m + 8];
            }
#pragma unroll
            for (int ni = 0; ni < 2; ni++) {
                int n = wns + ni * 8 + tg;
                bf[ni][0] = Ks[(kc + tk    ) * SQ + n];
                bf[ni][1] = Ks[(kc + tk + 4) * SQ + n];
            }
#pragma unroll
            for (int mi = 0; mi < 2; mi++)
#pragma unroll
                for (int ni = 0; ni < 2; ni++)
                    MMA_TF32(sacc[mi][ni], af[mi], bf[ni]);
        }

#pragma unroll
        for (int mi = 0; mi < 2; mi++) {
#pragma unroll
            for (int ni = 0; ni < 2; ni++) {
                int m0 = wms + mi * 16 + tg;
                int n0 = wns + ni * 8 + 2 * tk;
                long grow0 = q0 + m0;
                long gcol  = k0 + n0;
                float2 mk0 = *(const float2*)(Mask + grow0 * L + gcol);
                float2 mk1 = *(const float2*)(Mask + (grow0 + 8) * L + gcol);
                Ps[(n0    ) * SQ + m0    ] = __float_as_uint(fmaf(sacc[mi][ni][0], scale, mk0.x));
                Ps[(n0 + 1) * SQ + m0    ] = __float_as_uint(fmaf(sacc[mi][ni][1], scale, mk0.y));
                Ps[(n0    ) * SQ + m0 + 8] = __float_as_uint(fmaf(sacc[mi][ni][2], scale, mk1.x));
                Ps[(n0 + 1) * SQ + m0 + 8] = __float_as_uint(fmaf(sacc[mi][ni][3], scale, mk1.y));
            }
        }
        __syncthreads();

        // ---- online softmax: 4 lanes per row, interleaved columns (bank-conflict-free) ----
        {
            float mx = m_i;
#pragma unroll
            for (int i = 0; i < 16; i++) {
                int n = spart + 4 * i;
                mx = fmaxf(mx, __uint_as_float(Ps[n * SQ + srow]));
            }
            mx = fmaxf(mx, __shfl_xor_sync(0xffffffffu, mx, 1));
            mx = fmaxf(mx, __shfl_xor_sync(0xffffffffu, mx, 2));

            float al = expf(m_i - mx);
            float sum = 0.f;
#pragma unroll
            for (int i = 0; i < 16; i++) {
                int n = spart + 4 * i;
                float p = expf(__uint_as_float(Ps[n * SQ + srow]) - mx);
                sum += p;
                Ps[n * SQ + srow] = f2tf32(p);
            }
            sum += __shfl_xor_sync(0xffffffffu, sum, 1);
            sum += __shfl_xor_sync(0xffffffffu, sum, 2);

            m_i = mx;
            l_i = l_i * al + sum;
            if (spart == 0) arow[srow] = al;
        }
        __syncthreads();

#pragma unroll
        for (int mi = 0; mi < 2; mi++) {
            float al0 = arow[wmo + mi * 16 + tg];
            float al1 = arow[wmo + mi * 16 + tg + 8];
#pragma unroll
            for (int ni = 0; ni < 4; ni++) {
                Oacc[mi][ni][0] *= al0; Oacc[mi][ni][1] *= al0;
                Oacc[mi][ni][2] *= al1; Oacc[mi][ni][3] *= al1;
            }
        }
#pragma unroll
        for (int kc = 0; kc < TBN; kc += 8) {
            uint32_t af[2][4], bf[4][2];
#pragma unroll
            for (int mi = 0; mi < 2; mi++) {
                int m = wmo + mi * 16 + tg;
                af[mi][0] = Ps[(kc + tk    ) * SQ + m    ];
                af[mi][1] = Ps[(kc + tk    ) * SQ + m + 8];
                af[mi][2] = Ps[(kc + tk + 4) * SQ + m    ];
                af[mi][3] = Ps[(kc + tk + 4) * SQ + m + 8];
            }
#pragma unroll
            for (int ni = 0; ni < 4; ni++) {
                int d = wdo + ni * 8 + tg;
                bf[ni][0] = Vs[(kc + tk    ) * SV + d];
                bf[ni][1] = Vs[(kc + tk + 4) * SV + d];
            }
#pragma unroll
            for (int mi = 0; mi < 2; mi++)
#pragma unroll
                for (int ni = 0; ni < 4; ni++)
                    MMA_TF32(Oacc[mi][ni], af[mi], bf[ni]);
        }
        __syncthreads();
    }

    if (spart == 0) lrow[srow] = l_i;
    __syncthreads();

#pragma unroll
    for (int mi = 0; mi < 2; mi++) {
        int m0 = wmo + mi * 16 + tg;
        float inv0 = 1.f / lrow[m0];
        float inv1 = 1.f / lrow[m0 + 8];
#pragma unroll
        for (int ni = 0; ni < 4; ni++) {
            int d0 = wdo + ni * 8 + 2 * tk;
            float2 o0 = { Oacc[mi][ni][0] * inv0, Oacc[mi][ni][1] * inv0 };
            float2 o1 = { Oacc[mi][ni][2] * inv1, Oacc[mi][ni][3] * inv1 };
            *(float2*)(Op + (long)(q0 + m0    ) * HIDN + h * HD + d0) = o0;
            *(float2*)(Op + (long)(q0 + m0 + 8) * HIDN + h * HD + d0) = o1;
        }
    }
}
#define FLASH_TC_SMEM ((128*SQ + 128*SQ + TBN*SV + TBM*SQ) * 4 + 2 * 64 * 4)

// ---------------- RMSNorm ----------------
__global__ __launch_bounds__(256)
void rmsnorm_kernel(const float* __restrict__ x, const float* __restrict__ w,
                    float* __restrict__ out)
{
    long row = blockIdx.x;
    const float* xr = x + row * HIDN;
    float* o = out + row * HIDN;
    int t = threadIdx.x;
    __shared__ float part[256];
    float ss = 0.f;
    for (int c = t; c < HIDN; c += 256) { float v = xr[c]; ss += v * v; }
    part[t] = ss; __syncthreads();
    for (int w2 = 128; w2 > 0; w2 >>= 1) {
        if (t < w2) part[t] += part[t + w2];
        __syncthreads();
    }
    float inv = rsqrtf(part[0] / (float)HIDN + 1e-6f);
    for (int c = t; c < HIDN; c += 256) o[c] = xr[c] * inv * (1.f + w[c]);
}

// ---------------- RoPE table (accurate trig — semantics identical to the R7 fix) ----
__global__ __launch_bounds__(256)
void rope_table_kernel()
{
    int idx = blockIdx.x * 256 + threadIdx.x;
    if (idx >= S1 * 64) return;
    int d = idx & 63;
    int s = idx >> 6;
    float inv = __powf(10000.0f, -((float)(2 * d)) / 128.0f);
    float ang = (float)s * inv;
    double cd, sd;
    sincos((double)ang, &sd, &cd);
    g_COS[idx] = (float)cd;
    g_SIN[idx] = (float)sd;
}

__global__ __launch_bounds__(256)
void rope3_kernel(const float* __restrict__ in, float* __restrict__ out, int S)
{
    int idx = blockIdx.x * 256 + threadIdx.x;
    if (idx >= S * NH * 64) return;
    int d = idx & 63;
    int h = (idx >> 6) & 7;
    int s = idx >> 9;
    float c  = g_COS[s * 64 + d];
    float sn = g_SIN[s * 64 + d];
    const float* ir = in + (long)s * HIDN + h * HD;
    float* orow = out + (long)s * HIDN + h * HD;
    float x0 = ir[d], x1 = ir[d + 64];
    orow[d]      = x0 * c - x1 * sn;
    orow[d + 64] = x1 * c + x0 * sn;
}

// ---------------- gelu(tanh)(g) * u in-place ----------------
__global__ __launch_bounds__(256)
void gelumul2_kernel(float* __restrict__ g, const float* __restrict__ u, int n)
{
    int i = blockIdx.x * 256 + threadIdx.x;
    if (i >= n) return;
    float x = g[i];
    float z = 0.7978845608028654f * (x + 0.044715f * x * x * x);
    float th = 1.f - 2.f / (expf(2.f * z) + 1.f);
    float t = 0.5f * x * (1.f + th);
    g[i] = t * u[i];
}

// ---------------- host helpers ----------------
static void gemm_batch(const GB3& gb, int nz, bool has_e,
                       int M, int N, int K, int lda, int ldb, int ldc, int lde, float alpha)
{
    dim3 grid(N / 128, M / 128, nz);
    if (has_e) gemm4_kernel<true ><<<grid, 256>>>(gb, M, N, K, lda, ldb, ldc, lde, alpha);
    else       gemm4_kernel<false><<<grid, 256>>>(gb, M, N, K, lda, ldb, ldc, lde, alpha);
}

static void gemm1(const float* A, const float* B, float* C, const float* E, bool has_e,
                  int M, int N, int K, int lda, int ldb, int ldc, int lde, float alpha)
{
    GB3 gb{}; gb.e[0] = { A, B, C, E };
    gemm_batch(gb, 1, has_e, M, N, K, lda, ldb, ldc, lde, alpha);
}

extern "C" void kernel_launch(void* const* d_in, const int* in_sizes, int n_in,
                              void* d_out, int out_size)
{
    (void)in_sizes; (void)n_in; (void)out_size;

    const float* x[2]    = { (const float*)d_in[0], (const float*)d_in[1] };
    const float* mask[2] = { (const float*)d_in[2], (const float*)d_in[3] };
    const float* mixmask = (const float*)d_in[4];
    float* out = (float*)d_out;

    float *H, *H1, *Q, *K, *V, *QR, *KR, *ATTN, *G, *U;
    cudaGetSymbolAddress((void**)&H,    g_H);
    cudaGetSymbolAddress((void**)&H1,   g_H1);
    cudaGetSymbolAddress((void**)&Q,    g_Q);
    cudaGetSymbolAddress((void**)&K,    g_K);
    cudaGetSymbolAddress((void**)&V,    g_V);
    cudaGetSymbolAddress((void**)&QR,   g_QR);
    cudaGetSymbolAddress((void**)&KR,   g_KR);
    cudaGetSymbolAddress((void**)&ATTN, g_ATTN);
    cudaGetSymbolAddress((void**)&G,    g_G);
    cudaGetSymbolAddress((void**)&U,    g_U);

    cudaFuncSetAttribute(flash_tc_kernel, cudaFuncAttributeMaxDynamicSharedMemorySize, FLASH_TC_SMEM);

    const float scale = 0.08838834764831845f;

    rope_table_kernel<<<(S1 * 64 + 255) / 256, 256>>>();

    for (int e = 0; e < 2; e++) {
        const float* w_ln  = (const float*)d_in[5 + e * 9 + 0];
        const float* wq    = (const float*)d_in[5 + e * 9 + 1];
        const float* wk    = (const float*)d_in[5 + e * 9 + 2];
        const float* wv    = (const float*)d_in[5 + e * 9 + 3];
        const float* wo    = (const float*)d_in[5 + e * 9 + 4];
        const float* w_pln = (const float*)d_in[5 + e * 9 + 5];
        const float* wg    = (const float*)d_in[5 + e * 9 + 6];
        const float* wu    = (const float*)d_in[5 + e * 9 + 7];
        const float* wd    = (const float*)d_in[5 + e * 9 + 8];

        float* Qe = Q + (long)e * S1 * HIDN;
        float* Ke = K + (long)e * S1 * HIDN;
        float* Ve = V + (long)e * S1 * HIDN;

        rmsnorm_kernel<<<S1, 256>>>(x[e], w_ln, H);

        {
            GB3 gb{};
            gb.e[0] = { H, wq, Qe, nullptr };
            gb.e[1] = { H, wk, Ke, nullptr };
            gb.e[2] = { H, wv, Ve, nullptr };
            gemm_batch(gb, 3, false, S1, HIDN, HIDN, HIDN, HIDN, HIDN, 0, 1.f);
        }

        rope3_kernel<<<(S1 * NH * 64 + 255) / 256, 256>>>(Qe, QR, S1);
        rope3_kernel<<<(S1 * NH * 64 + 255) / 256, 256>>>(Ke, KR, S1);

        {
            dim3 grid(S1 / TBM, 1, NH);
            flash_tc_kernel<<<grid, 256, FLASH_TC_SMEM>>>(QR, KR, Ve, mask[e], ATTN, S1, scale, 1);
        }

        gemm1(ATTN, wo, H1, x[e], true, S1, HIDN, HIDN, HIDN, HIDN, HIDN, HIDN, 1.f);

        rmsnorm_kernel<<<S1, 256>>>(H1, w_pln, H);

        {
            GB3 gb{};
            gb.e[0] = { H, wg, G, nullptr };
            gb.e[1] = { H, wu, U, nullptr };
            gemm_batch(gb, 2, false, S1, INTER_, HIDN, HIDN, INTER_, INTER_, 0, 1.f);
        }
        gelumul2_kernel<<<(S1 * INTER_ + 255) / 256, 256>>>(G, U, S1 * INTER_);
        gemm1(G, wd, out + (long)e * S1 * HIDN, H1, true,
              S1, HIDN, INTER_, INTER_, HIDN, HIDN, HIDN, 1.f);
    }

    // ---- mix attention over concatenated pre-RoPE q/k/v ----
    {
        dim3 grid(S2 / TBM, 1, NH);
        flash_tc_kernel<<<grid, 256, FLASH_TC_SMEM>>>(Q, K, V, mixmask, ATTN, S2, scale, 0);
    }

    // out[e] += mixed[e] @ wo_e — one batched launch (C==E elementwise, safe)
    {
        GB3 gb{};
        gb.e[0] = { ATTN,                 (const float*)d_in[5 + 0 * 9 + 4], out,                 out };
        gb.e[1] = { ATTN + (long)S1*HIDN, (const float*)d_in[5 + 1 * 9 + 4], out + (long)S1*HIDN, out + (long)S1*HIDN };
        gemm_batch(gb, 2, true, S1, HIDN, HIDN, HIDN, HIDN, HIDN, HIDN, 1.f);
    }
}

// round 14
// speedup vs baseline: 4.4698x; 1.5433x over previous
#include <cuda_runtime.h>
#include <cuda_bf16.h>
#include <cstdint>

#define S1   2048
#define S2   4096
#define HIDN 1024
#define NH   8
#define HD   128
#define INTER_ 4096

// ---------------- scratch ----------------
__device__ float g_H [S1 * HIDN];
__device__ float g_H1[S1 * HIDN];
__device__ float g_Q [S2 * HIDN];
__device__ float g_K [S2 * HIDN];
__device__ float g_V [S2 * HIDN];
__device__ float g_QR[S1 * HIDN];
__device__ float g_KR[S1 * HIDN];
__device__ float g_ATTN[S2 * HIDN];
__device__ float g_G[S1 * INTER_];
__device__ float g_U[S1 * INTER_];
__device__ float g_COS[S1 * 64];
__device__ float g_SIN[S1 * 64];

__device__ __forceinline__ uint32_t f2tf32(float f)
{
    uint32_t r;
    asm("cvt.rna.tf32.f32 %0, %1;" : "=r"(r) : "f"(f));
    return r;
}

__device__ __forceinline__ void cp16(void* smem_dst, const void* gmem_src)
{
    uint32_t s = (uint32_t)__cvta_generic_to_shared(smem_dst);
    asm volatile("cp.async.cg.shared.global [%0], [%1], 16;" :: "r"(s), "l"(gmem_src));
}
#define CP_COMMIT() asm volatile("cp.async.commit_group;")
#define CP_WAIT0()  asm volatile("cp.async.wait_group 0;")

#define MMA_TF32(acc, a, b) \
    asm volatile( \
        "mma.sync.aligned.m16n8k8.row.col.f32.tf32.tf32.f32 " \
        "{%0,%1,%2,%3}, {%4,%5,%6,%7}, {%8,%9}, {%0,%1,%2,%3};" \
        : "+f"(acc[0]), "+f"(acc[1]), "+f"(acc[2]), "+f"(acc[3]) \
        : "r"(a[0]), "r"(a[1]), "r"(a[2]), "r"(a[3]), "r"(b[0]), "r"(b[1]))

// ---------------- batched TF32 tensor-core GEMM (unchanged from passing R13) --------
struct GBEnt { const float* A; const float* B; float* C; const float* E; };
struct GB3   { GBEnt e[3]; };

template<bool HAS_E>
__global__ __launch_bounds__(256, 2)
void gemm4_kernel(GB3 gb,
                  int M, int N, int K, int lda, int ldb, int ldc, int lde, float alpha)
{
    __shared__ uint32_t As[2][16][136];
    __shared__ uint32_t Bs[2][16][136];

    const float* __restrict__ A = gb.e[blockIdx.z].A;
    const float* __restrict__ B = gb.e[blockIdx.z].B;
    float* __restrict__ C       = gb.e[blockIdx.z].C;
    const float* __restrict__ E = gb.e[blockIdx.z].E;

    const int bm = blockIdx.y * 128;
    const int bn = blockIdx.x * 128;
    const int tid  = threadIdx.x;
    const int wid  = tid >> 5;
    const int lane = tid & 31;
    const int wm = (wid & 1) * 64;
    const int wn = (wid >> 1) * 32;
    const int tg = lane >> 2;
    const int tk = lane & 3;

    const int lr = tid >> 2;
    const int lc = (tid & 3) * 4;
    const int br = tid >> 5;
    const int bc = (tid & 31) * 4;

    float acc[4][4][4];
#pragma unroll
    for (int mi = 0; mi < 4; mi++)
#pragma unroll
        for (int ni = 0; ni < 4; ni++)
#pragma unroll
            for (int r = 0; r < 4; r++) acc[mi][ni][r] = 0.f;

#pragma unroll
    for (int p = 0; p < 2; p++) {
        float4 va = *(const float4*)(A + (long)(bm + lr + p * 64) * lda + lc);
        As[0][lc + 0][lr + p * 64] = f2tf32(va.x);
        As[0][lc + 1][lr + p * 64] = f2tf32(va.y);
        As[0][lc + 2][lr + p * 64] = f2tf32(va.z);
        As[0][lc + 3][lr + p * 64] = f2tf32(va.w);
        float4 vb = *(const float4*)(B + (long)(br + p * 8) * ldb + (bn + bc));
        uint4 ub = { f2tf32(vb.x), f2tf32(vb.y), f2tf32(vb.z), f2tf32(vb.w) };
        *(uint4*)&Bs[0][br + p * 8][bc] = ub;
    }
    __syncthreads();

    int cur = 0;
    for (int k0 = 0; k0 < K; k0 += 16) {
        float4 pa[2], pb[2];
        const bool has_next = (k0 + 16) < K;
        if (has_next) {
#pragma unroll
            for (int p = 0; p < 2; p++) {
                pa[p] = *(const float4*)(A + (long)(bm + lr + p * 64) * lda + (k0 + 16 + lc));
                pb[p] = *(const float4*)(B + (long)(k0 + 16 + br + p * 8) * ldb + (bn + bc));
            }
        }

#pragma unroll
        for (int kc = 0; kc < 16; kc += 8) {
            uint32_t afr[4][4];
#pragma unroll
            for (int mi = 0; mi < 4; mi++) {
                int mb = wm + mi * 16 + tg;
                afr[mi][0] = As[cur][kc + tk    ][mb    ];
                afr[mi][1] = As[cur][kc + tk    ][mb + 8];
                afr[mi][2] = As[cur][kc + tk + 4][mb    ];
                afr[mi][3] = As[cur][kc + tk + 4][mb + 8];
            }
            uint32_t bfr[4][2];
#pragma unroll
            for (int ni = 0; ni < 4; ni++) {
                int nb = wn + ni * 8 + tg;
                bfr[ni][0] = Bs[cur][kc + tk    ][nb];
                bfr[ni][1] = Bs[cur][kc + tk + 4][nb];
            }
#pragma unroll
            for (int mi = 0; mi < 4; mi++)
#pragma unroll
                for (int ni = 0; ni < 4; ni++)
                    MMA_TF32(acc[mi][ni], afr[mi], bfr[ni]);
        }

        if (has_next) {
            int nxt = cur ^ 1;
#pragma unroll
            for (int p = 0; p < 2; p++) {
                As[nxt][lc + 0][lr + p * 64] = f2tf32(pa[p].x);
                As[nxt][lc + 1][lr + p * 64] = f2tf32(pa[p].y);
                As[nxt][lc + 2][lr + p * 64] = f2tf32(pa[p].z);
                As[nxt][lc + 3][lr + p * 64] = f2tf32(pa[p].w);
                uint4 ub = { f2tf32(pb[p].x), f2tf32(pb[p].y), f2tf32(pb[p].z), f2tf32(pb[p].w) };
                *(uint4*)&Bs[nxt][br + p * 8][bc] = ub;
            }
            __syncthreads();
            cur = nxt;
        }
    }

#pragma unroll
    for (int mi = 0; mi < 4; mi++) {
#pragma unroll
        for (int ni = 0; ni < 4; ni++) {
            long row0 = bm + wm + mi * 16 + tg;
            long row1 = row0 + 8;
            int col = bn + wn + ni * 8 + 2 * tk;
            float2 v0 = { alpha * acc[mi][ni][0], alpha * acc[mi][ni][1] };
            float2 v1 = { alpha * acc[mi][ni][2], alpha * acc[mi][ni][3] };
            if (HAS_E) {
                float2 e0 = *(const float2*)(E + row0 * lde + col);
                float2 e1 = *(const float2*)(E + row1 * lde + col);
                v0.x += e0.x; v0.y += e0.y;
                v1.x += e1.x; v1.y += e1.y;
            }
            *(float2*)(C + row0 * ldc + col) = v0;
            *(float2*)(C + row1 * ldc + col) = v1;
        }
    }
}

// ---------------- tensor-core flash attention, cp.async pipelined ----------------
// Q: [m][d] stride 132 (A-frag bank 4tg+tk, conflict-free)
// K: [n][d] stride 132 double-buffered (B-frag bank 4tg+tk, conflict-free)
// V: [n][d] stride 136 double-buffered (B-frag bank 8tk+tg, conflict-free)
// Raw f32 operands feed tf32 MMA (RZ truncation); P is RNA-converted in softmax.
#define TBM 64
#define TBN 64
#define SQS 132
#define SVS 136
#define SPS 72

__global__ __launch_bounds__(256)
void flash_tc_kernel(const float* __restrict__ Qp, const float* __restrict__ Kp,
                     const float* __restrict__ Vp, const float* __restrict__ Mask,
                     float* __restrict__ Op, int L, float scale, int causal)
{
    extern __shared__ uint32_t smu[];
    uint32_t* Qs = smu;                        // [64][132]
    uint32_t* Ks = Qs + TBM * SQS;             // [2][64][132]
    uint32_t* Vs = Ks + 2 * TBN * SQS;         // [2][64][136]
    uint32_t* Ps = Vs + 2 * TBN * SVS;         // [n][m] stride 72
    float* arow = (float*)(Ps + TBM * SPS);
    float* lrow = arow + 64;

    const int h   = blockIdx.z;
    const int q0  = blockIdx.x * TBM;
    const int tid = threadIdx.x;
    const int wid = tid >> 5;
    const int lane = tid & 31;
    const int tg = lane >> 2;
    const int tk = lane & 3;
    const int wms = (wid & 1) * 32, wns = (wid >> 1) * 16;
    const int wmo = (wid & 1) * 32, wdo = (wid >> 1) * 32;
    const int srow = tid >> 2;
    const int spart = tid & 3;

    const float* Qh = Qp + h * HD;
    const float* Kh = Kp + h * HD;
    const float* Vh = Vp + h * HD;

    // preload Q + K0/V0 via cp.async
    for (int i = tid; i < TBM * 32; i += 256) {
        int m = i >> 5, c = (i & 31) * 4;
        cp16(Qs + m * SQS + c, Qh + (long)(q0 + m) * HIDN + c);
    }
    for (int i = tid; i < TBN * 32; i += 256) {
        int n = i >> 5, c = (i & 31) * 4;
        cp16(Ks + n * SQS + c, Kh + (long)n * HIDN + c);
        cp16(Vs + n * SVS + c, Vh + (long)n * HIDN + c);
    }
    CP_COMMIT();
    CP_WAIT0();

    float m_i = -3.4e38f, l_i = 0.f;
    float Oacc[2][4][4];
#pragma unroll
    for (int mi = 0; mi < 2; mi++)
#pragma unroll
        for (int ni = 0; ni < 4; ni++)
#pragma unroll
            for (int r = 0; r < 4; r++) Oacc[mi][ni][r] = 0.f;

    __syncthreads();

    const int ktiles = causal ? (q0 / TBN + 1) : (L / TBN);
    int buf = 0;
    for (int t = 0; t < ktiles; t++) {
        const int k0 = t * TBN;

        // prefetch next K/V tile into the other buffer (latency hidden by this iter)
        if (t + 1 < ktiles) {
            int kn = k0 + TBN;
            uint32_t* Kd = Ks + (buf ^ 1) * TBN * SQS;
            uint32_t* Vd = Vs + (buf ^ 1) * TBN * SVS;
            for (int i = tid; i < TBN * 32; i += 256) {
                int n = i >> 5, c = (i & 31) * 4;
                cp16(Kd + n * SQS + c, Kh + (long)(kn + n) * HIDN + c);
                cp16(Vd + n * SVS + c, Vh + (long)(kn + n) * HIDN + c);
            }
            CP_COMMIT();
        }
        const uint32_t* Kb = Ks + buf * TBN * SQS;
        const uint32_t* Vb = Vs + buf * TBN * SVS;

        // ---- S = Q·K^T ----
        float sacc[2][2][4];
#pragma unroll
        for (int mi = 0; mi < 2; mi++)
#pragma unroll
            for (int ni = 0; ni < 2; ni++)
#pragma unroll
                for (int r = 0; r < 4; r++) sacc[mi][ni][r] = 0.f;

#pragma unroll
        for (int kc = 0; kc < 128; kc += 8) {
            uint32_t af[2][4], bf[2][2];
#pragma unroll
            for (int mi = 0; mi < 2; mi++) {
                int m = wms + mi * 16 + tg;
                af[mi][0] = Qs[(m    ) * SQS + kc + tk    ];
                af[mi][1] = Qs[(m + 8) * SQS + kc + tk    ];
                af[mi][2] = Qs[(m    ) * SQS + kc + tk + 4];
                af[mi][3] = Qs[(m + 8) * SQS + kc + tk + 4];
            }
#pragma unroll
            for (int ni = 0; ni < 2; ni++) {
                int n = wns + ni * 8 + tg;
                bf[ni][0] = Kb[n * SQS + kc + tk    ];
                bf[ni][1] = Kb[n * SQS + kc + tk + 4];
            }
#pragma unroll
            for (int mi = 0; mi < 2; mi++)
#pragma unroll
                for (int ni = 0; ni < 2; ni++)
                    MMA_TF32(sacc[mi][ni], af[mi], bf[ni]);
        }

#pragma unroll
        for (int mi = 0; mi < 2; mi++) {
#pragma unroll
            for (int ni = 0; ni < 2; ni++) {
                int m0 = wms + mi * 16 + tg;
                int n0 = wns + ni * 8 + 2 * tk;
                long grow0 = q0 + m0;
                long gcol  = k0 + n0;
                float2 mk0 = *(const float2*)(Mask + grow0 * L + gcol);
                float2 mk1 = *(const float2*)(Mask + (grow0 + 8) * L + gcol);
                Ps[(n0    ) * SPS + m0    ] = __float_as_uint(fmaf(sacc[mi][ni][0], scale, mk0.x));
                Ps[(n0 + 1) * SPS + m0    ] = __float_as_uint(fmaf(sacc[mi][ni][1], scale, mk0.y));
                Ps[(n0    ) * SPS + m0 + 8] = __float_as_uint(fmaf(sacc[mi][ni][2], scale, mk1.x));
                Ps[(n0 + 1) * SPS + m0 + 8] = __float_as_uint(fmaf(sacc[mi][ni][3], scale, mk1.y));
            }
        }
        __syncthreads();

        // ---- online softmax: 4 lanes per row ----
        {
            float mx = m_i;
#pragma unroll
            for (int i = 0; i < 16; i++) {
                int n = spart + 4 * i;
                mx = fmaxf(mx, __uint_as_float(Ps[n * SPS + srow]));
            }
            mx = fmaxf(mx, __shfl_xor_sync(0xffffffffu, mx, 1));
            mx = fmaxf(mx, __shfl_xor_sync(0xffffffffu, mx, 2));

            float al = expf(m_i - mx);
            float sum = 0.f;
#pragma unroll
            for (int i = 0; i < 16; i++) {
                int n = spart + 4 * i;
                float p = expf(__uint_as_float(Ps[n * SPS + srow]) - mx);
                sum += p;
                Ps[n * SPS + srow] = f2tf32(p);
            }
            sum += __shfl_xor_sync(0xffffffffu, sum, 1);
            sum += __shfl_xor_sync(0xffffffffu, sum, 2);

            m_i = mx;
            l_i = l_i * al + sum;
            if (spart == 0) arow[srow] = al;
        }
        __syncthreads();

        // ---- O = O*alpha + P·V ----
#pragma unroll
        for (int mi = 0; mi < 2; mi++) {
            float al0 = arow[wmo + mi * 16 + tg];
            float al1 = arow[wmo + mi * 16 + tg + 8];
#pragma unroll
            for (int ni = 0; ni < 4; ni++) {
                Oacc[mi][ni][0] *= al0; Oacc[mi][ni][1] *= al0;
                Oacc[mi][ni][2] *= al1; Oacc[mi][ni][3] *= al1;
            }
        }
#pragma unroll
        for (int kc = 0; kc < TBN; kc += 8) {
            uint32_t af[2][4], bf[4][2];
#pragma unroll
            for (int mi = 0; mi < 2; mi++) {
                int m = wmo + mi * 16 + tg;
                af[mi][0] = Ps[(kc + tk    ) * SPS + m    ];
                af[mi][1] = Ps[(kc + tk    ) * SPS + m + 8];
                af[mi][2] = Ps[(kc + tk + 4) * SPS + m    ];
                af[mi][3] = Ps[(kc + tk + 4) * SPS + m + 8];
            }
#pragma unroll
            for (int ni = 0; ni < 4; ni++) {
                int d = wdo + ni * 8 + tg;
                bf[ni][0] = Vb[(kc + tk    ) * SVS + d];
                bf[ni][1] = Vb[(kc + tk + 4) * SVS + d];
            }
#pragma unroll
            for (int mi = 0; mi < 2; mi++)
#pragma unroll
                for (int ni = 0; ni < 4; ni++)
                    MMA_TF32(Oacc[mi][ni], af[mi], bf[ni]);
        }

        CP_WAIT0();          // next tile's K/V landed (issued at iter start)
        __syncthreads();
        buf ^= 1;
    }

    if (spart == 0) lrow[srow] = l_i;
    __syncthreads();

#pragma unroll
    for (int mi = 0; mi < 2; mi++) {
        int m0 = wmo + mi * 16 + tg;
        float inv0 = 1.f / lrow[m0];
        float inv1 = 1.f / lrow[m0 + 8];
#pragma unroll
        for (int ni = 0; ni < 4; ni++) {
            int d0 = wdo + ni * 8 + 2 * tk;
            float2 o0 = { Oacc[mi][ni][0] * inv0, Oacc[mi][ni][1] * inv0 };
            float2 o1 = { Oacc[mi][ni][2] * inv1, Oacc[mi][ni][3] * inv1 };
            *(float2*)(Op + (long)(q0 + m0    ) * HIDN + h * HD + d0) = o0;
            *(float2*)(Op + (long)(q0 + m0 + 8) * HIDN + h * HD + d0) = o1;
        }
    }
}
#define FLASH_TC_SMEM ((TBM*SQS + 2*TBN*SQS + 2*TBN*SVS + TBM*SPS) * 4 + 2 * 64 * 4)

// ---------------- RMSNorm ----------------
__global__ __launch_bounds__(256)
void rmsnorm_kernel(const float* __restrict__ x, const float* __restrict__ w,
                    float* __restrict__ out)
{
    long row = blockIdx.x;
    const float* xr = x + row * HIDN;
    float* o = out + row * HIDN;
    int t = threadIdx.x;
    __shared__ float part[256];
    float ss = 0.f;
    for (int c = t; c < HIDN; c += 256) { float v = xr[c]; ss += v * v; }
    part[t] = ss; __syncthreads();
    for (int w2 = 128; w2 > 0; w2 >>= 1) {
        if (t < w2) part[t] += part[t + w2];
        __syncthreads();
    }
    float inv = rsqrtf(part[0] / (float)HIDN + 1e-6f);
    for (int c = t; c < HIDN; c += 256) o[c] = xr[c] * inv * (1.f + w[c]);
}

// ---------------- RoPE table (accurate trig — semantics identical to the R7 fix) ----
__global__ __launch_bounds__(256)
void rope_table_kernel()
{
    int idx = blockIdx.x * 256 + threadIdx.x;
    if (idx >= S1 * 64) return;
    int d = idx & 63;
    int s = idx >> 6;
    float inv = __powf(10000.0f, -((float)(2 * d)) / 128.0f);
    float ang = (float)s * inv;
    double cd, sd;
    sincos((double)ang, &sd, &cd);
    g_COS[idx] = (float)cd;
    g_SIN[idx] = (float)sd;
}

// one launch handles both Q (y=0) and K (y=1)
__global__ __launch_bounds__(256)
void rope4_kernel(const float* __restrict__ inq, float* __restrict__ outq,
                  const float* __restrict__ ink, float* __restrict__ outk, int S)
{
    int idx = blockIdx.x * 256 + threadIdx.x;
    if (idx >= S * NH * 64) return;
    const float* in = blockIdx.y ? ink : inq;
    float* out      = blockIdx.y ? outk : outq;
    int d = idx & 63;
    int h = (idx >> 6) & 7;
    int s = idx >> 9;
    float c  = g_COS[s * 64 + d];
    float sn = g_SIN[s * 64 + d];
    const float* ir = in + (long)s * HIDN + h * HD;
    float* orow = out + (long)s * HIDN + h * HD;
    float x0 = ir[d], x1 = ir[d + 64];
    orow[d]      = x0 * c - x1 * sn;
    orow[d + 64] = x1 * c + x0 * sn;
}

// ---------------- gelu(tanh)(g) * u in-place ----------------
__global__ __launch_bounds__(256)
void gelumul2_kernel(float* __restrict__ g, const float* __restrict__ u, int n)
{
    int i = blockIdx.x * 256 + threadIdx.x;
    if (i >= n) return;
    float x = g[i];
    float z = 0.7978845608028654f * (x + 0.044715f * x * x * x);
    float th = 1.f - 2.f / (expf(2.f * z) + 1.f);
    float t = 0.5f * x * (1.f + th);
    g[i] = t * u[i];
}

// ---------------- host helpers ----------------
static void gemm_batch(const GB3& gb, int nz, bool has_e,
                       int M, int N, int K, int lda, int ldb, int ldc, int lde, float alpha)
{
    dim3 grid(N / 128, M / 128, nz);
    if (has_e) gemm4_kernel<true ><<<grid, 256>>>(gb, M, N, K, lda, ldb, ldc, lde, alpha);
    else       gemm4_kernel<false><<<grid, 256>>>(gb, M, N, K, lda, ldb, ldc, lde, alpha);
}

static void gemm1(const float* A, const float* B, float* C, const float* E, bool has_e,
                  int M, int N, int K, int lda, int ldb, int ldc, int lde, float alpha)
{
    GB3 gb{}; gb.e[0] = { A, B, C, E };
    gemm_batch(gb, 1, has_e, M, N, K, lda, ldb, ldc, lde, alpha);
}

extern "C" void kernel_launch(void* const* d_in, const int* in_sizes, int n_in,
                              void* d_out, int out_size)
{
    (void)in_sizes; (void)n_in; (void)out_size;

    const float* x[2]    = { (const float*)d_in[0], (const float*)d_in[1] };
    const float* mask[2] = { (const float*)d_in[2], (const float*)d_in[3] };
    const float* mixmask = (const float*)d_in[4];
    float* out = (float*)d_out;

    float *H, *H1, *Q, *K, *V, *QR, *KR, *ATTN, *G, *U;
    cudaGetSymbolAddress((void**)&H,    g_H);
    cudaGetSymbolAddress((void**)&H1,   g_H1);
    cudaGetSymbolAddress((void**)&Q,    g_Q);
    cudaGetSymbolAddress((void**)&K,    g_K);
    cudaGetSymbolAddress((void**)&V,    g_V);
    cudaGetSymbolAddress((void**)&QR,   g_QR);
    cudaGetSymbolAddress((void**)&KR,   g_KR);
    cudaGetSymbolAddress((void**)&ATTN, g_ATTN);
    cudaGetSymbolAddress((void**)&G,    g_G);
    cudaGetSymbolAddress((void**)&U,    g_U);

    cudaFuncSetAttribute(flash_tc_kernel, cudaFuncAttributeMaxDynamicSharedMemorySize, FLASH_TC_SMEM);

    const float scale = 0.08838834764831845f;

    rope_table_kernel<<<(S1 * 64 + 255) / 256, 256>>>();

    for (int e = 0; e < 2; e++) {
        const float* w_ln  = (const float*)d_in[5 + e * 9 + 0];
        const float* wq    = (const float*)d_in[5 + e * 9 + 1];
        const float* wk    = (const float*)d_in[5 + e * 9 + 2];
        const float* wv    = (const float*)d_in[5 + e * 9 + 3];
        const float* wo    = (const float*)d_in[5 + e * 9 + 4];
        const float* w_pln = (const float*)d_in[5 + e * 9 + 5];
        const float* wg    = (const float*)d_in[5 + e * 9 + 6];
        const float* wu    = (const float*)d_in[5 + e * 9 + 7];
        const float* wd    = (const float*)d_in[5 + e * 9 + 8];

        float* Qe = Q + (long)e * S1 * HIDN;
        float* Ke = K + (long)e * S1 * HIDN;
        float* Ve = V + (long)e * S1 * HIDN;

        rmsnorm_kernel<<<S1, 256>>>(x[e], w_ln, H);

        {
            GB3 gb{};
            gb.e[0] = { H, wq, Qe, nullptr };
            gb.e[1] = { H, wk, Ke, nullptr };
            gb.e[2] = { H, wv, Ve, nullptr };
            gemm_batch(gb, 3, false, S1, HIDN, HIDN, HIDN, HIDN, HIDN, 0, 1.f);
        }

        {
            dim3 grid((S1 * NH * 64 + 255) / 256, 2);
            rope4_kernel<<<grid, 256>>>(Qe, QR, Ke, KR, S1);
        }

        {
            dim3 grid(S1 / TBM, 1, NH);
            flash_tc_kernel<<<grid, 256, FLASH_TC_SMEM>>>(QR, KR, Ve, mask[e], ATTN, S1, scale, 1);
        }

        gemm1(ATTN, wo, H1, x[e], true, S1, HIDN, HIDN, HIDN, HIDN, HIDN, HIDN, 1.f);

        rmsnorm_kernel<<<S1, 256>>>(H1, w_pln, H);

        {
            GB3 gb{};
            gb.e[0] = { H, wg, G, nullptr };
            gb.e[1] = { H, wu, U, nullptr };
            gemm_batch(gb, 2, false, S1, INTER_, HIDN, HIDN, INTER_, INTER_, 0, 1.f);
        }
        gelumul2_kernel<<<(S1 * INTER_ + 255) / 256, 256>>>(G, U, S1 * INTER_);
        gemm1(G, wd, out + (long)e * S1 * HIDN, H1, true,
              S1, HIDN, INTER_, INTER_, HIDN, HIDN, HIDN, 1.f);
    }

    // ---- mix attention over concatenated pre-RoPE q/k/v ----
    {
        dim3 grid(S2 / TBM, 1, NH);
        flash_tc_kernel<<<grid, 256, FLASH_TC_SMEM>>>(Q, K, V, mixmask, ATTN, S2, scale, 0);
    }

    // out[e] += mixed[e] @ wo_e — one batched launch (C==E elementwise, safe)
    {
        GB3 gb{};
        gb.e[0] = { ATTN,                 (const float*)d_in[5 + 0 * 9 + 4], out,                 out };
        gb.e[1] = { ATTN + (long)S1*HIDN, (const float*)d_in[5 + 1 * 9 + 4], out + (long)S1*HIDN, out + (long)S1*HIDN };
        gemm_batch(gb, 2, true, S1, HIDN, HIDN, HIDN, HIDN, HIDN, HIDN, 1.f);
    }
}

// round 16
// speedup vs baseline: 4.6125x; 1.0319x over previous
#include <cuda_runtime.h>
#include <cuda_bf16.h>
#include <cstdint>

#define S1   2048
#define S2   4096
#define HIDN 1024
#define NH   8
#define HD   128
#define INTER_ 4096

// ---------------- scratch ----------------
__device__ float g_H [S1 * HIDN];
__device__ float g_H1[S1 * HIDN];
__device__ float g_Q [S2 * HIDN];
__device__ float g_K [S2 * HIDN];
__device__ float g_V [S2 * HIDN];
__device__ float g_QR[S1 * HIDN];
__device__ float g_KR[S1 * HIDN];
__device__ float g_ATTN[S2 * HIDN];
__device__ float g_G[S1 * INTER_];
__device__ float g_U[S1 * INTER_];
__device__ float g_COS[S1 * 64];
__device__ float g_SIN[S1 * 64];

__device__ __forceinline__ uint32_t f2tf32(float f)
{
    uint32_t r;
    asm("cvt.rna.tf32.f32 %0, %1;" : "=r"(r) : "f"(f));
    return r;
}

__device__ __forceinline__ void cp16(void* smem_dst, const void* gmem_src)
{
    uint32_t s = (uint32_t)__cvta_generic_to_shared(smem_dst);
    asm volatile("cp.async.cg.shared.global [%0], [%1], 16;" :: "r"(s), "l"(gmem_src));
}
#define CP_COMMIT() asm volatile("cp.async.commit_group;")
#define CP_WAIT0()  asm volatile("cp.async.wait_group 0;")

#define MMA_TF32(acc, a, b) \
    asm volatile( \
        "mma.sync.aligned.m16n8k8.row.col.f32.tf32.tf32.f32 " \
        "{%0,%1,%2,%3}, {%4,%5,%6,%7}, {%8,%9}, {%0,%1,%2,%3};" \
        : "+f"(acc[0]), "+f"(acc[1]), "+f"(acc[2]), "+f"(acc[3]) \
        : "r"(a[0]), "r"(a[1]), "r"(a[2]), "r"(a[3]), "r"(b[0]), "r"(b[1]))

// ---------------- batched TF32 GEMM, cp.async pipelined, no cvt ----------------
// Per z-slice: C = alpha*A@B (+E).  A: MxK row-major, B: KxN row-major.
// Smem: A-tile [m][k] stride 20 (bank (20m+k)%32: conflict-free fragments),
//       B-tile [k][n] stride 132 (bank (4k+n)%32: conflict-free fragments).
// Raw fp32 bits feed tf32 MMA (RZ truncation — validated in flash, rel_err +1e-6).
struct GBEnt { const float* A; const float* B; float* C; const float* E; };
struct GB3   { GBEnt e[3]; };

template<bool HAS_E>
__global__ __launch_bounds__(256, 2)
void gemm5_kernel(GB3 gb,
                  int M, int N, int K, int lda, int ldb, int ldc, int lde, float alpha)
{
    __shared__ uint32_t As[2][128][20];   // [buf][m][k]
    __shared__ uint32_t Bs[2][16][132];   // [buf][k][n]

    const float* __restrict__ A = gb.e[blockIdx.z].A;
    const float* __restrict__ B = gb.e[blockIdx.z].B;
    float* __restrict__ C       = gb.e[blockIdx.z].C;
    const float* __restrict__ E = gb.e[blockIdx.z].E;

    const int bm = blockIdx.y * 128;
    const int bn = blockIdx.x * 128;
    const int tid  = threadIdx.x;
    const int wid  = tid >> 5;
    const int lane = tid & 31;
    const int wm = (wid & 1) * 64;
    const int wn = (wid >> 1) * 32;
    const int tg = lane >> 2;
    const int tk = lane & 3;

    // cp.async load mapping
    const int ar = tid >> 2;             // A row 0..63 (passes +0,+64)
    const int ac = (tid & 3) * 4;        // A k-chunk col 0,4,8,12
    const int brow = tid >> 5;           // B k-row 0..7 (passes +0,+8)
    const int bcol = (tid & 31) * 4;     // B n col 0..124

    float acc[4][4][4];
#pragma unroll
    for (int mi = 0; mi < 4; mi++)
#pragma unroll
        for (int ni = 0; ni < 4; ni++)
#pragma unroll
            for (int r = 0; r < 4; r++) acc[mi][ni][r] = 0.f;

    // prologue: tile 0 -> buf 0
#pragma unroll
    for (int p = 0; p < 2; p++) {
        int r = ar + p * 64;
        cp16(&As[0][r][ac], A + (long)(bm + r) * lda + ac);
        int kr = brow + p * 8;
        cp16(&Bs[0][kr][bcol], B + (long)kr * ldb + bn + bcol);
    }
    CP_COMMIT();
    CP_WAIT0();
    __syncthreads();

    int cur = 0;
    for (int k0 = 0; k0 < K; k0 += 16) {
        const bool has_next = (k0 + 16) < K;
        if (has_next) {
            int nxt = cur ^ 1;
#pragma unroll
            for (int p = 0; p < 2; p++) {
                int r = ar + p * 64;
                cp16(&As[nxt][r][ac], A + (long)(bm + r) * lda + (k0 + 16 + ac));
                int kr = brow + p * 8;
                cp16(&Bs[nxt][kr][bcol], B + (long)(k0 + 16 + kr) * ldb + bn + bcol);
            }
            CP_COMMIT();
        }

#pragma unroll
        for (int kc = 0; kc < 16; kc += 8) {
            uint32_t afr[4][4];
#pragma unroll
            for (int mi = 0; mi < 4; mi++) {
                int mb = wm + mi * 16 + tg;
                afr[mi][0] = As[cur][mb    ][kc + tk    ];
                afr[mi][1] = As[cur][mb + 8][kc + tk    ];
                afr[mi][2] = As[cur][mb    ][kc + tk + 4];
                afr[mi][3] = As[cur][mb + 8][kc + tk + 4];
            }
            uint32_t bfr[4][2];
#pragma unroll
            for (int ni = 0; ni < 4; ni++) {
                int nb = wn + ni * 8 + tg;
                bfr[ni][0] = Bs[cur][kc + tk    ][nb];
                bfr[ni][1] = Bs[cur][kc + tk + 4][nb];
            }
#pragma unroll
            for (int mi = 0; mi < 4; mi++)
#pragma unroll
                for (int ni = 0; ni < 4; ni++)
                    MMA_TF32(acc[mi][ni], afr[mi], bfr[ni]);
        }

        if (has_next) {
            CP_WAIT0();
            __syncthreads();
            cur ^= 1;
        }
    }

#pragma unroll
    for (int mi = 0; mi < 4; mi++) {
#pragma unroll
        for (int ni = 0; ni < 4; ni++) {
            long row0 = bm + wm + mi * 16 + tg;
            long row1 = row0 + 8;
            int col = bn + wn + ni * 8 + 2 * tk;
            float2 v0 = { alpha * acc[mi][ni][0], alpha * acc[mi][ni][1] };
            float2 v1 = { alpha * acc[mi][ni][2], alpha * acc[mi][ni][3] };
            if (HAS_E) {
                float2 e0 = *(const float2*)(E + row0 * lde + col);
                float2 e1 = *(const float2*)(E + row1 * lde + col);
                v0.x += e0.x; v0.y += e0.y;
                v1.x += e1.x; v1.y += e1.y;
            }
            *(float2*)(C + row0 * ldc + col) = v0;
            *(float2*)(C + row1 * ldc + col) = v1;
        }
    }
}

// ---------------- tensor-core flash attention, cp.async pipelined (R14, unchanged) --
#define TBM 64
#define TBN 64
#define SQS 132
#define SVS 136
#define SPS 72

__global__ __launch_bounds__(256)
void flash_tc_kernel(const float* __restrict__ Qp, const float* __restrict__ Kp,
                     const float* __restrict__ Vp, const float* __restrict__ Mask,
                     float* __restrict__ Op, int L, float scale, int causal)
{
    extern __shared__ uint32_t smu[];
    uint32_t* Qs = smu;
    uint32_t* Ks = Qs + TBM * SQS;
    uint32_t* Vs = Ks + 2 * TBN * SQS;
    uint32_t* Ps = Vs + 2 * TBN * SVS;
    float* arow = (float*)(Ps + TBM * SPS);
    float* lrow = arow + 64;

    const int h   = blockIdx.z;
    const int q0  = blockIdx.x * TBM;
    const int tid = threadIdx.x;
    const int wid = tid >> 5;
    const int lane = tid & 31;
    const int tg = lane >> 2;
    const int tk = lane & 3;
    const int wms = (wid & 1) * 32, wns = (wid >> 1) * 16;
    const int wmo = (wid & 1) * 32, wdo = (wid >> 1) * 32;
    const int srow = tid >> 2;
    const int spart = tid & 3;

    const float* Qh = Qp + h * HD;
    const float* Kh = Kp + h * HD;
    const float* Vh = Vp + h * HD;

    for (int i = tid; i < TBM * 32; i += 256) {
        int m = i >> 5, c = (i & 31) * 4;
        cp16(Qs + m * SQS + c, Qh + (long)(q0 + m) * HIDN + c);
    }
    for (int i = tid; i < TBN * 32; i += 256) {
        int n = i >> 5, c = (i & 31) * 4;
        cp16(Ks + n * SQS + c, Kh + (long)n * HIDN + c);
        cp16(Vs + n * SVS + c, Vh + (long)n * HIDN + c);
    }
    CP_COMMIT();
    CP_WAIT0();

    float m_i = -3.4e38f, l_i = 0.f;
    float Oacc[2][4][4];
#pragma unroll
    for (int mi = 0; mi < 2; mi++)
#pragma unroll
        for (int ni = 0; ni < 4; ni++)
#pragma unroll
            for (int r = 0; r < 4; r++) Oacc[mi][ni][r] = 0.f;

    __syncthreads();

    const int ktiles = causal ? (q0 / TBN + 1) : (L / TBN);
    int buf = 0;
    for (int t = 0; t < ktiles; t++) {
        const int k0 = t * TBN;

        if (t + 1 < ktiles) {
            int kn = k0 + TBN;
            uint32_t* Kd = Ks + (buf ^ 1) * TBN * SQS;
            uint32_t* Vd = Vs + (buf ^ 1) * TBN * SVS;
            for (int i = tid; i < TBN * 32; i += 256) {
                int n = i >> 5, c = (i & 31) * 4;
                cp16(Kd + n * SQS + c, Kh + (long)(kn + n) * HIDN + c);
                cp16(Vd + n * SVS + c, Vh + (long)(kn + n) * HIDN + c);
            }
            CP_COMMIT();
        }
        const uint32_t* Kb = Ks + buf * TBN * SQS;
        const uint32_t* Vb = Vs + buf * TBN * SVS;

        float sacc[2][2][4];
#pragma unroll
        for (int mi = 0; mi < 2; mi++)
#pragma unroll
            for (int ni = 0; ni < 2; ni++)
#pragma unroll
                for (int r = 0; r < 4; r++) sacc[mi][ni][r] = 0.f;

#pragma unroll
        for (int kc = 0; kc < 128; kc += 8) {
            uint32_t af[2][4], bf[2][2];
#pragma unroll
            for (int mi = 0; mi < 2; mi++) {
                int m = wms + mi * 16 + tg;
                af[mi][0] = Qs[(m    ) * SQS + kc + tk    ];
                af[mi][1] = Qs[(m + 8) * SQS + kc + tk    ];
                af[mi][2] = Qs[(m    ) * SQS + kc + tk + 4];
                af[mi][3] = Qs[(m + 8) * SQS + kc + tk + 4];
            }
#pragma unroll
            for (int ni = 0; ni < 2; ni++) {
                int n = wns + ni * 8 + tg;
                bf[ni][0] = Kb[n * SQS + kc + tk    ];
                bf[ni][1] = Kb[n * SQS + kc + tk + 4];
            }
#pragma unroll
            for (int mi = 0; mi < 2; mi++)
#pragma unroll
                for (int ni = 0; ni < 2; ni++)
                    MMA_TF32(sacc[mi][ni], af[mi], bf[ni]);
        }

#pragma unroll
        for (int mi = 0; mi < 2; mi++) {
#pragma unroll
            for (int ni = 0; ni < 2; ni++) {
                int m0 = wms + mi * 16 + tg;
                int n0 = wns + ni * 8 + 2 * tk;
                long grow0 = q0 + m0;
                long gcol  = k0 + n0;
                float2 mk0 = *(const float2*)(Mask + grow0 * L + gcol);
                float2 mk1 = *(const float2*)(Mask + (grow0 + 8) * L + gcol);
                Ps[(n0    ) * SPS + m0    ] = __float_as_uint(fmaf(sacc[mi][ni][0], scale, mk0.x));
                Ps[(n0 + 1) * SPS + m0    ] = __float_as_uint(fmaf(sacc[mi][ni][1], scale, mk0.y));
                Ps[(n0    ) * SPS + m0 + 8] = __float_as_uint(fmaf(sacc[mi][ni][2], scale, mk1.x));
                Ps[(n0 + 1) * SPS + m0 + 8] = __float_as_uint(fmaf(sacc[mi][ni][3], scale, mk1.y));
            }
        }
        __syncthreads();

        {
            float mx = m_i;
#pragma unroll
            for (int i = 0; i < 16; i++) {
                int n = spart + 4 * i;
                mx = fmaxf(mx, __uint_as_float(Ps[n * SPS + srow]));
            }
            mx = fmaxf(mx, __shfl_xor_sync(0xffffffffu, mx, 1));
            mx = fmaxf(mx, __shfl_xor_sync(0xffffffffu, mx, 2));

            float al = expf(m_i - mx);
            float sum = 0.f;
#pragma unroll
            for (int i = 0; i < 16; i++) {
                int n = spart + 4 * i;
                float p = expf(__uint_as_float(Ps[n * SPS + srow]) - mx);
                sum += p;
                Ps[n * SPS + srow] = f2tf32(p);
            }
            sum += __shfl_xor_sync(0xffffffffu, sum, 1);
            sum += __shfl_xor_sync(0xffffffffu, sum, 2);

            m_i = mx;
            l_i = l_i * al + sum;
            if (spart == 0) arow[srow] = al;
        }
        __syncthreads();

#pragma unroll
        for (int mi = 0; mi < 2; mi++) {
            float al0 = arow[wmo + mi * 16 + tg];
            float al1 = arow[wmo + mi * 16 + tg + 8];
#pragma unroll
            for (int ni = 0; ni < 4; ni++) {
                Oacc[mi][ni][0] *= al0; Oacc[mi][ni][1] *= al0;
                Oacc[mi][ni][2] *= al1; Oacc[mi][ni][3] *= al1;
            }
        }
#pragma unroll
        for (int kc = 0; kc < TBN; kc += 8) {
            uint32_t af[2][4], bf[4][2];
#pragma unroll
            for (int mi = 0; mi < 2; mi++) {
                int m = wmo + mi * 16 + tg;
                af[mi][0] = Ps[(kc + tk    ) * SPS + m    ];
                af[mi][1] = Ps[(kc + tk    ) * SPS + m + 8];
                af[mi][2] = Ps[(kc + tk + 4) * SPS + m    ];
                af[mi][3] = Ps[(kc + tk + 4) * SPS + m + 8];
            }
#pragma unroll
            for (int ni = 0; ni < 4; ni++) {
                int d = wdo + ni * 8 + tg;
                bf[ni][0] = Vb[(kc + tk    ) * SVS + d];
                bf[ni][1] = Vb[(kc + tk + 4) * SVS + d];
            }
#pragma unroll
            for (int mi = 0; mi < 2; mi++)
#pragma unroll
                for (int ni = 0; ni < 4; ni++)
                    MMA_TF32(Oacc[mi][ni], af[mi], bf[ni]);
        }

        CP_WAIT0();
        __syncthreads();
        buf ^= 1;
    }

    if (spart == 0) lrow[srow] = l_i;
    __syncthreads();

#pragma unroll
    for (int mi = 0; mi < 2; mi++) {
        int m0 = wmo + mi * 16 + tg;
        float inv0 = 1.f / lrow[m0];
        float inv1 = 1.f / lrow[m0 + 8];
#pragma unroll
        for (int ni = 0; ni < 4; ni++) {
            int d0 = wdo + ni * 8 + 2 * tk;
            float2 o0 = { Oacc[mi][ni][0] * inv0, Oacc[mi][ni][1] * inv0 };
            float2 o1 = { Oacc[mi][ni][2] * inv1, Oacc[mi][ni][3] * inv1 };
            *(float2*)(Op + (long)(q0 + m0    ) * HIDN + h * HD + d0) = o0;
            *(float2*)(Op + (long)(q0 + m0 + 8) * HIDN + h * HD + d0) = o1;
        }
    }
}
#define FLASH_TC_SMEM ((TBM*SQS + 2*TBN*SQS + 2*TBN*SVS + TBM*SPS) * 4 + 2 * 64 * 4)

// ---------------- RMSNorm ----------------
__global__ __launch_bounds__(256)
void rmsnorm_kernel(const float* __restrict__ x, const float* __restrict__ w,
                    float* __restrict__ out)
{
    long row = blockIdx.x;
    const float* xr = x + row * HIDN;
    float* o = out + row * HIDN;
    int t = threadIdx.x;
    __shared__ float part[256];
    float ss = 0.f;
    for (int c = t; c < HIDN; c += 256) { float v = xr[c]; ss += v * v; }
    part[t] = ss; __syncthreads();
    for (int w2 = 128; w2 > 0; w2 >>= 1) {
        if (t < w2) part[t] += part[t + w2];
        __syncthreads();
    }
    float inv = rsqrtf(part[0] / (float)HIDN + 1e-6f);
    for (int c = t; c < HIDN; c += 256) o[c] = xr[c] * inv * (1.f + w[c]);
}

// ---------------- RoPE table (accurate trig — semantics identical to the R7 fix) ----
__global__ __launch_bounds__(256)
void rope_table_kernel()
{
    int idx = blockIdx.x * 256 + threadIdx.x;
    if (idx >= S1 * 64) return;
    int d = idx & 63;
    int s = idx >> 6;
    float inv = __powf(10000.0f, -((float)(2 * d)) / 128.0f);
    float ang = (float)s * inv;
    double cd, sd;
    sincos((double)ang, &sd, &cd);
    g_COS[idx] = (float)cd;
    g_SIN[idx] = (float)sd;
}

__global__ __launch_bounds__(256)
void rope4_kernel(const float* __restrict__ inq, float* __restrict__ outq,
                  const float* __restrict__ ink, float* __restrict__ outk, int S)
{
    int idx = blockIdx.x * 256 + threadIdx.x;
    if (idx >= S * NH * 64) return;
    const float* in = blockIdx.y ? ink : inq;
    float* out      = blockIdx.y ? outk : outq;
    int d = idx & 63;
    int h = (idx >> 6) & 7;
    int s = idx >> 9;
    float c  = g_COS[s * 64 + d];
    float sn = g_SIN[s * 64 + d];
    const float* ir = in + (long)s * HIDN + h * HD;
    float* orow = out + (long)s * HIDN + h * HD;
    float x0 = ir[d], x1 = ir[d + 64];
    orow[d]      = x0 * c - x1 * sn;
    orow[d + 64] = x1 * c + x0 * sn;
}

// ---------------- gelu(tanh)(g) * u in-place ----------------
__global__ __launch_bounds__(256)
void gelumul2_kernel(float* __restrict__ g, const float* __restrict__ u, int n)
{
    int i = blockIdx.x * 256 + threadIdx.x;
    if (i >= n) return;
    float x = g[i];
    float z = 0.7978845608028654f * (x + 0.044715f * x * x * x);
    float th = 1.f - 2.f / (expf(2.f * z) + 1.f);
    float t = 0.5f * x * (1.f + th);
    g[i] = t * u[i];
}

// ---------------- host helpers ----------------
static void gemm_batch(const GB3& gb, int nz, bool has_e,
                       int M, int N, int K, int lda, int ldb, int ldc, int lde, float alpha)
{
    dim3 grid(N / 128, M / 128, nz);
    if (has_e) gemm5_kernel<true ><<<grid, 256>>>(gb, M, N, K, lda, ldb, ldc, lde, alpha);
    else       gemm5_kernel<false><<<grid, 256>>>(gb, M, N, K, lda, ldb, ldc, lde, alpha);
}

static void gemm1(const float* A, const float* B, float* C, const float* E, bool has_e,
                  int M, int N, int K, int lda, int ldb, int ldc, int lde, float alpha)
{
    GB3 gb{}; gb.e[0] = { A, B, C, E };
    gemm_batch(gb, 1, has_e, M, N, K, lda, ldb, ldc, lde, alpha);
}

extern "C" void kernel_launch(void* const* d_in, const int* in_sizes, int n_in,
                              void* d_out, int out_size)
{
    (void)in_sizes; (void)n_in; (void)out_size;

    const float* x[2]    = { (const float*)d_in[0], (const float*)d_in[1] };
    const float* mask[2] = { (const float*)d_in[2], (const float*)d_in[3] };
    const float* mixmask = (const float*)d_in[4];
    float* out = (float*)d_out;

    float *H, *H1, *Q, *K, *V, *QR, *KR, *ATTN, *G, *U;
    cudaGetSymbolAddress((void**)&H,    g_H);
    cudaGetSymbolAddress((void**)&H1,   g_H1);
    cudaGetSymbolAddress((void**)&Q,    g_Q);
    cudaGetSymbolAddress((void**)&K,    g_K);
    cudaGetSymbolAddress((void**)&V,    g_V);
    cudaGetSymbolAddress((void**)&QR,   g_QR);
    cudaGetSymbolAddress((void**)&KR,   g_KR);
    cudaGetSymbolAddress((void**)&ATTN, g_ATTN);
    cudaGetSymbolAddress((void**)&G,    g_G);
    cudaGetSymbolAddress((void**)&U,    g_U);

    cudaFuncSetAttribute(flash_tc_kernel, cudaFuncAttributeMaxDynamicSharedMemorySize, FLASH_TC_SMEM);

    const float scale = 0.08838834764831845f;

    rope_table_kernel<<<(S1 * 64 + 255) / 256, 256>>>();

    for (int e = 0; e < 2; e++) {
        const float* w_ln  = (const float*)d_in[5 + e * 9 + 0];
        const float* wq    = (const float*)d_in[5 + e * 9 + 1];
        const float* wk    = (const float*)d_in[5 + e * 9 + 2];
        const float* wv    = (const float*)d_in[5 + e * 9 + 3];
        const float* wo    = (const float*)d_in[5 + e * 9 + 4];
        const float* w_pln = (const float*)d_in[5 + e * 9 + 5];
        const float* wg    = (const float*)d_in[5 + e * 9 + 6];
        const float* wu    = (const float*)d_in[5 + e * 9 + 7];
        const float* wd    = (const float*)d_in[5 + e * 9 + 8];

        float* Qe = Q + (long)e * S1 * HIDN;
        float* Ke = K + (long)e * S1 * HIDN;
        float* Ve = V + (long)e * S1 * HIDN;

        rmsnorm_kernel<<<S1, 256>>>(x[e], w_ln, H);

        {
            GB3 gb{};
            gb.e[0] = { H, wq, Qe, nullptr };
            gb.e[1] = { H, wk, Ke, nullptr };
            gb.e[2] = { H, wv, Ve, nullptr };
            gemm_batch(gb, 3, false, S1, HIDN, HIDN, HIDN, HIDN, HIDN, 0, 1.f);
        }

        {
            dim3 grid((S1 * NH * 64 + 255) / 256, 2);
            rope4_kernel<<<grid, 256>>>(Qe, QR, Ke, KR, S1);
        }

        {
            dim3 grid(S1 / TBM, 1, NH);
            flash_tc_kernel<<<grid, 256, FLASH_TC_SMEM>>>(QR, KR, Ve, mask[e], ATTN, S1, scale, 1);
        }

        gemm1(ATTN, wo, H1, x[e], true, S1, HIDN, HIDN, HIDN, HIDN, HIDN, HIDN, 1.f);

        rmsnorm_kernel<<<S1, 256>>>(H1, w_pln, H);

        {
            GB3 gb{};
            gb.e[0] = { H, wg, G, nullptr };
            gb.e[1] = { H, wu, U, nullptr };
            gemm_batch(gb, 2, false, S1, INTER_, HIDN, HIDN, INTER_, INTER_, 0, 1.f);
        }
        gelumul2_kernel<<<(S1 * INTER_ + 255) / 256, 256>>>(G, U, S1 * INTER_);
        gemm1(G, wd, out + (long)e * S1 * HIDN, H1, true,
              S1, HIDN, INTER_, INTER_, HIDN, HIDN, HIDN, 1.f);
    }

    // ---- mix attention over concatenated pre-RoPE q/k/v ----
    {
        dim3 grid(S2 / TBM, 1, NH);
        flash_tc_kernel<<<grid, 256, FLASH_TC_SMEM>>>(Q, K, V, mixmask, ATTN, S2, scale, 0);
    }

    // out[e] += mixed[e] @ wo_e — one batched launch (C==E elementwise, safe)
    {
        GB3 gb{};
        gb.e[0] = { ATTN,                 (const float*)d_in[5 + 0 * 9 + 4], out,                 out };
        gb.e[1] = { ATTN + (long)S1*HIDN, (const float*)d_in[5 + 1 * 9 + 4], out + (long)S1*HIDN, out + (long)S1*HIDN };
        gemm_batch(gb, 2, true, S1, HIDN, HIDN, HIDN, HIDN, HIDN, HIDN, 1.f);
    }
}